// round 1
// baseline (speedup 1.0000x reference)
#include <cuda_runtime.h>
#include <cuda_bf16.h>

// ---------------------------------------------------------------------------
// SynthesisBlock: two modulated 3x3 convs + noise + bias + leaky + pixelshuffle
// Shapes: B=16, H=W=64, C_IN=256, C_OUT2_total=512, W_DIM=128
// Strategy: modulation folded into input load (conv(x*s, K)), demod folded
// into epilogue. Implicit-GEMM fp32 SIMT baseline.
// ---------------------------------------------------------------------------

#define B_SZ 16
#define H_SZ 64
#define W_SZ 64
#define CIN  256
#define N1   256   // conv1 output channels
#define N2   512   // conv2 output channels (pre pixel-shuffle)
#define WDIM 128

// ---- device scratch (allocation-free rule: __device__ globals) ----
__device__ float g_s1[B_SZ * CIN];
__device__ float g_s2[B_SZ * CIN];
__device__ float g_d1[B_SZ * N1];
__device__ float g_d2[B_SZ * N2];
__device__ float g_k1sq[CIN * N1];
__device__ float g_k2sq[CIN * N2];
__device__ float g_inter[B_SZ * H_SZ * W_SZ * CIN];   // 67 MB intermediate

// ---------------------------------------------------------------------------
// style: s[b,ci] = w[b,:] @ affine_w[:,ci] + affine_b[ci]
// ---------------------------------------------------------------------------
template<int CONV>
__global__ void style_kernel(const float* __restrict__ w,
                             const float* __restrict__ aw,
                             const float* __restrict__ ab)
{
    int b  = blockIdx.x;
    int ci = threadIdx.x;
    float sum = ab[ci];
    const float* wr = w + b * WDIM;
    #pragma unroll 8
    for (int k = 0; k < WDIM; ++k)
        sum += wr[k] * aw[k * CIN + ci];
    if (CONV == 0) g_s1[b * CIN + ci] = sum;
    else           g_s2[b * CIN + ci] = sum;
}

// ---------------------------------------------------------------------------
// ksq: Ksq[ci,co] = sum over 9 taps of kernel[kh,kw,ci,co]^2
// ---------------------------------------------------------------------------
template<int CONV, int NTOT>
__global__ void ksq_kernel(const float* __restrict__ kern)
{
    int idx = blockIdx.x * blockDim.x + threadIdx.x;   // idx = ci*NTOT + co
    if (idx >= CIN * NTOT) return;
    float s = 0.f;
    #pragma unroll
    for (int p = 0; p < 9; ++p) {
        float v = kern[p * CIN * NTOT + idx];
        s += v * v;
    }
    if (CONV == 0) g_k1sq[idx] = s;
    else           g_k2sq[idx] = s;
}

// ---------------------------------------------------------------------------
// demod: d[b,co] = rsqrt( sum_ci s[b,ci]^2 * Ksq[ci,co] + 1e-8 )
// ---------------------------------------------------------------------------
template<int CONV, int NTOT>
__global__ void demod_kernel()
{
    __shared__ float ssq[CIN];
    int b  = blockIdx.y;
    int co = blockIdx.x * blockDim.x + threadIdx.x;
    const float* st = (CONV == 0) ? g_s1 : g_s2;
    if (threadIdx.x < CIN) {
        float s = st[b * CIN + threadIdx.x];
        ssq[threadIdx.x] = s * s;
    }
    __syncthreads();
    const float* kq = (CONV == 0) ? g_k1sq : g_k2sq;
    float sum = 0.f;
    #pragma unroll 8
    for (int ci = 0; ci < CIN; ++ci)
        sum += ssq[ci] * kq[ci * NTOT + co];
    float d = rsqrtf(sum + 1e-8f);
    if (CONV == 0) g_d1[b * NTOT + co] = d;
    else           g_d2[b * NTOT + co] = d;
}

// ---------------------------------------------------------------------------
// Modulated conv as implicit GEMM.
// CTA: one (b, h) row of 64 pixels x 128 output channels.
// K loop: 3x3 taps x 16-channel chunks. A-tile modulated by style on load.
// Epilogue: *demod + noise*nscale + bias, leaky(0.2); conv2 pixel-shuffles
// directly into d_out.
// ---------------------------------------------------------------------------
template<int CONV, int NTOT>
__global__ __launch_bounds__(256)
void conv_mod_kernel(const float* __restrict__ x_param,   // conv1 input (d_in[0]); ignored for conv2
                     const float* __restrict__ kern,      // [3,3,256,NTOT]
                     const float* __restrict__ noise,     // [B,H,W]
                     const float* __restrict__ nscale,    // [1]
                     const float* __restrict__ bias,      // [NTOT]
                     float* __restrict__ outp)            // d_out for conv2; ignored for conv1
{
    const int b   = blockIdx.z;
    const int h   = blockIdx.y;
    const int co0 = blockIdx.x * 128;
    const int tid = threadIdx.x;

    const float* __restrict__ xin   = (CONV == 0) ? x_param : g_inter;
    const float* __restrict__ style = (CONV == 0) ? g_s1 : g_s2;
    const float* __restrict__ demod = (CONV == 0) ? g_d1 : g_d2;

    __shared__ float sS[CIN];
    __shared__ float As[16][64];
    __shared__ float Bs[16][128];

    sS[tid] = style[b * CIN + tid];
    __syncthreads();

    float acc[4][8];
    #pragma unroll
    for (int i = 0; i < 4; ++i)
        #pragma unroll
        for (int j = 0; j < 8; ++j) acc[i][j] = 0.f;

    // A-loader mapping: each thread loads 4 consecutive ci for one pixel
    const int m  = tid & 63;   // pixel 0..63
    const int kq = tid >> 6;   // ci sub-group 0..3
    // compute mapping
    const int ty = tid >> 4;   // pixel group 0..15 -> pixels ty*4..ty*4+3
    const int tx = tid & 15;   // co group 0..15   -> cos tx*8..tx*8+7

    for (int kh = 0; kh < 3; ++kh) {
        const int srcH = h + kh - 1;
        if (srcH < 0 || srcH >= H_SZ) continue;
        const float* xrow = xin + ((size_t)(b * H_SZ + srcH) * W_SZ) * CIN;
        for (int kw = 0; kw < 3; ++kw) {
            const int  srcW = m + kw - 1;
            const bool vw   = (srcW >= 0) && (srcW < W_SZ);
            const float* kbase = kern + (size_t)((kh * 3 + kw) * CIN) * NTOT + co0;

            for (int cc = 0; cc < CIN; cc += 16) {
                // ---- global loads (before barrier, to overlap) ----
                float4 av = make_float4(0.f, 0.f, 0.f, 0.f);
                if (vw) {
                    av = *reinterpret_cast<const float4*>(xrow + srcW * CIN + cc + kq * 4);
                    const float4 sv = *reinterpret_cast<const float4*>(&sS[cc + kq * 4]);
                    av.x *= sv.x; av.y *= sv.y; av.z *= sv.z; av.w *= sv.w;
                }
                const int lin0 = tid, lin1 = tid + 256;
                const float4 bv0 = *reinterpret_cast<const float4*>(
                    kbase + (size_t)(cc + (lin0 >> 5)) * NTOT + ((lin0 & 31) << 2));
                const float4 bv1 = *reinterpret_cast<const float4*>(
                    kbase + (size_t)(cc + (lin1 >> 5)) * NTOT + ((lin1 & 31) << 2));

                __syncthreads();   // previous tile fully consumed
                As[kq * 4 + 0][m] = av.x;
                As[kq * 4 + 1][m] = av.y;
                As[kq * 4 + 2][m] = av.z;
                As[kq * 4 + 3][m] = av.w;
                *reinterpret_cast<float4*>(&Bs[lin0 >> 5][(lin0 & 31) << 2]) = bv0;
                *reinterpret_cast<float4*>(&Bs[lin1 >> 5][(lin1 & 31) << 2]) = bv1;
                __syncthreads();

                // ---- MACs: 16 k-steps, 4x8 register tile ----
                #pragma unroll
                for (int k = 0; k < 16; ++k) {
                    const float4 a  = *reinterpret_cast<const float4*>(&As[k][ty * 4]);
                    const float4 b0 = *reinterpret_cast<const float4*>(&Bs[k][tx * 8]);
                    const float4 b1 = *reinterpret_cast<const float4*>(&Bs[k][tx * 8 + 4]);
                    const float ar[4] = {a.x, a.y, a.z, a.w};
                    const float br[8] = {b0.x, b0.y, b0.z, b0.w, b1.x, b1.y, b1.z, b1.w};
                    #pragma unroll
                    for (int i = 0; i < 4; ++i)
                        #pragma unroll
                        for (int j = 0; j < 8; ++j)
                            acc[i][j] = fmaf(ar[i], br[j], acc[i][j]);
                }
            }
        }
    }

    // ---- epilogue ----
    const float ns = nscale[0];
    const int   nbase = (b * H_SZ + h) * W_SZ;
    float dreg[8];
    #pragma unroll
    for (int j = 0; j < 8; ++j)
        dreg[j] = demod[b * NTOT + co0 + tx * 8 + j];

    #pragma unroll
    for (int i = 0; i < 4; ++i) {
        const int   w    = ty * 4 + i;
        const float nadd = noise[nbase + w] * ns;
        #pragma unroll
        for (int j = 0; j < 8; ++j) {
            const int co = co0 + tx * 8 + j;
            float v = acc[i][j] * dreg[j] + nadd + bias[co];
            v = (v > 0.f) ? v : 0.2f * v;
            if (CONV == 0) {
                g_inter[((size_t)(b * H_SZ + h) * W_SZ + w) * CIN + co] = v;
            } else {
                // pixel shuffle: c=co (0..511): sh=c>>8, sw=(c>>7)&1, cc=c&127
                const int sh = co >> 8;
                const int sw = (co >> 7) & 1;
                const int c2 = co & 127;
                outp[(((size_t)(b * 128 + 2 * h + sh)) * 128 + (2 * w + sw)) * 128 + c2] = v;
            }
        }
    }
}

// ---------------------------------------------------------------------------
// launch
// ---------------------------------------------------------------------------
extern "C" void kernel_launch(void* const* d_in, const int* in_sizes, int n_in,
                              void* d_out, int out_size)
{
    const float* x     = (const float*)d_in[0];
    const float* w     = (const float*)d_in[1];
    const float* a1w   = (const float*)d_in[2];
    const float* a1b   = (const float*)d_in[3];
    const float* k1    = (const float*)d_in[4];
    const float* ns1   = (const float*)d_in[5];
    const float* b1    = (const float*)d_in[6];
    const float* a2w   = (const float*)d_in[7];
    const float* a2b   = (const float*)d_in[8];
    const float* k2    = (const float*)d_in[9];
    const float* ns2   = (const float*)d_in[10];
    const float* b2    = (const float*)d_in[11];
    const float* noi1  = (const float*)d_in[12];
    const float* noi2  = (const float*)d_in[13];
    float* outp = (float*)d_out;

    // styles
    style_kernel<0><<<B_SZ, CIN>>>(w, a1w, a1b);
    style_kernel<1><<<B_SZ, CIN>>>(w, a2w, a2b);

    // kernel squared sums
    ksq_kernel<0, N1><<<(CIN * N1 + 255) / 256, 256>>>(k1);
    ksq_kernel<1, N2><<<(CIN * N2 + 255) / 256, 256>>>(k2);

    // demod factors
    {
        dim3 g1(N1 / 256, B_SZ); demod_kernel<0, N1><<<g1, 256>>>();
        dim3 g2(N2 / 256, B_SZ); demod_kernel<1, N2><<<g2, 256>>>();
    }

    // conv1: x -> g_inter
    {
        dim3 grid(N1 / 128, H_SZ, B_SZ);
        conv_mod_kernel<0, N1><<<grid, 256>>>(x, k1, noi1, ns1, b1, nullptr);
    }
    // conv2: g_inter -> d_out (pixel shuffled)
    {
        dim3 grid(N2 / 128, H_SZ, B_SZ);
        conv_mod_kernel<1, N2><<<grid, 256>>>(x, k2, noi2, ns2, b2, outp);
    }
}

// round 3
// speedup vs baseline: 4.1779x; 4.1779x over previous
#include <cuda_runtime.h>
#include <cuda_fp16.h>
#include <cstdint>

// ---------------------------------------------------------------------------
// SynthesisBlock via mma.sync (HMMA) fp16 hi/lo 3-plane split GEMMs.
// (tcgen05 unavailable: harness PTX target is sm_103, not sm_103a.)
// ---------------------------------------------------------------------------
#define B_SZ 16
#define H_SZ 64
#define W_SZ 64
#define CIN  256
#define N1   256
#define N2   512
#define WDIM 128
#define PW   66          // padded H/W

// ---- device scratch ----
__device__ float g_s1[B_SZ * CIN];
__device__ float g_s2[B_SZ * CIN];
__device__ float g_d1[B_SZ * N1];
__device__ float g_d2[B_SZ * N2];
__device__ float g_k1sq[CIN * N1];
__device__ float g_k2sq[CIN * N2];
__device__ __half g_xp_h [B_SZ * PW * PW * CIN];   // conv1 input, modulated by s1, hi plane
__device__ __half g_xp_l [B_SZ * PW * PW * CIN];   // lo plane
__device__ __half g_x2p_h[B_SZ * PW * PW * CIN];   // conv2 input (h * s2), hi
__device__ __half g_x2p_l[B_SZ * PW * PW * CIN];
__device__ __half g_w1h[9 * N1 * CIN];             // [tap][n][ci]
__device__ __half g_w1l[9 * N1 * CIN];
__device__ __half g_w2h[9 * N2 * CIN];
__device__ __half g_w2l[9 * N2 * CIN];

// ---------------------------------------------------------------------------
// low-level helpers (sm_80-class features only)
// ---------------------------------------------------------------------------
__device__ __forceinline__ uint32_t smem_to_u32(const void* p) {
    uint32_t a;
    asm("{ .reg .u64 t; cvta.to.shared.u64 t, %1; cvt.u32.u64 %0, t; }" : "=r"(a) : "l"(p));
    return a;
}

#define CPA16(dst, src) \
    asm volatile("cp.async.cg.shared.global [%0], [%1], 16;" :: "r"(dst), "l"(src))
#define CPA_COMMIT() asm volatile("cp.async.commit_group;" ::: "memory")
#define CPA_WAIT_1() asm volatile("cp.async.wait_group 1;" ::: "memory")
#define CPA_WAIT_0() asm volatile("cp.async.wait_group 0;" ::: "memory")

#define LDSM4(r, addr) \
    asm volatile("ldmatrix.sync.aligned.m8n8.x4.shared.b16 {%0,%1,%2,%3}, [%4];" \
        : "=r"((r)[0]), "=r"((r)[1]), "=r"((r)[2]), "=r"((r)[3]) : "r"(addr))

#define MMA16816(d, a, b0_, b1_) \
    asm volatile("mma.sync.aligned.m16n8k16.row.col.f32.f16.f16.f32 " \
        "{%0,%1,%2,%3}, {%4,%5,%6,%7}, {%8,%9}, {%0,%1,%2,%3};" \
        : "+f"((d)[0]), "+f"((d)[1]), "+f"((d)[2]), "+f"((d)[3]) \
        : "r"((a)[0]), "r"((a)[1]), "r"((a)[2]), "r"((a)[3]), "r"(b0_), "r"(b1_))

// ---------------------------------------------------------------------------
// prepare kernels
// ---------------------------------------------------------------------------
template<int CONV>
__global__ void style_kernel(const float* __restrict__ w,
                             const float* __restrict__ aw,
                             const float* __restrict__ ab)
{
    int b = blockIdx.x, ci = threadIdx.x;
    float sum = ab[ci];
    const float* wr = w + b * WDIM;
    #pragma unroll 8
    for (int k = 0; k < WDIM; ++k) sum += wr[k] * aw[k * CIN + ci];
    if (CONV == 0) g_s1[b * CIN + ci] = sum; else g_s2[b * CIN + ci] = sum;
}

template<int CONV, int NTOT>
__global__ void ksq_kernel(const float* __restrict__ kern)
{
    int idx = blockIdx.x * blockDim.x + threadIdx.x;
    if (idx >= CIN * NTOT) return;
    float s = 0.f;
    #pragma unroll
    for (int p = 0; p < 9; ++p) { float v = kern[p * CIN * NTOT + idx]; s += v * v; }
    if (CONV == 0) g_k1sq[idx] = s; else g_k2sq[idx] = s;
}

template<int CONV, int NTOT>
__global__ void demod_kernel()
{
    __shared__ float ssq[CIN];
    int b = blockIdx.y;
    int co = blockIdx.x * blockDim.x + threadIdx.x;
    const float* st = (CONV == 0) ? g_s1 : g_s2;
    if (threadIdx.x < CIN) { float s = st[b * CIN + threadIdx.x]; ssq[threadIdx.x] = s * s; }
    __syncthreads();
    const float* kq = (CONV == 0) ? g_k1sq : g_k2sq;
    float sum = 0.f;
    #pragma unroll 8
    for (int ci = 0; ci < CIN; ++ci) sum += ssq[ci] * kq[ci * NTOT + co];
    float d = rsqrtf(sum + 1e-8f);
    if (CONV == 0) g_d1[b * NTOT + co] = d; else g_d2[b * NTOT + co] = d;
}

// weight transpose + fp16 hi/lo split: out[tap][n][ci]
template<int CONV, int NTOT>
__global__ void wsplit_kernel(const float* __restrict__ kern)
{
    int idx = blockIdx.x * blockDim.x + threadIdx.x;   // over 9*CIN*NTOT
    if (idx >= 9 * CIN * NTOT) return;
    int tap = idx / (CIN * NTOT);
    int r   = idx % (CIN * NTOT);
    int ci  = r / NTOT;
    int n   = r % NTOT;
    float v = kern[idx];
    __half hi = __float2half_rn(v);
    __half lo = __float2half_rn(v - __half2float(hi));
    size_t o = ((size_t)tap * NTOT + n) * CIN + ci;
    if (CONV == 0) { g_w1h[o] = hi; g_w1l[o] = lo; }
    else           { g_w2h[o] = hi; g_w2l[o] = lo; }
}

// pad + modulate-by-s1 + fp16 split for conv1 input; zero x2pad borders too
__global__ void pad_kernel(const float* __restrict__ x)
{
    int pix = blockIdx.x;                 // 0 .. B*PW*PW-1
    int b  = pix / (PW * PW);
    int r  = pix % (PW * PW);
    int hp = r / PW, wp = r % PW;
    int ci = threadIdx.x;
    bool interior = (hp >= 1) && (hp <= H_SZ) && (wp >= 1) && (wp <= W_SZ);
    float v = 0.f;
    if (interior)
        v = x[(((size_t)b * H_SZ + (hp - 1)) * W_SZ + (wp - 1)) * CIN + ci] * g_s1[b * CIN + ci];
    __half hi = __float2half_rn(v);
    __half lo = __float2half_rn(v - __half2float(hi));
    size_t o = (size_t)pix * CIN + ci;
    g_xp_h[o] = hi; g_xp_l[o] = lo;
    if (!interior) { g_x2p_h[o] = __float2half_rn(0.f); g_x2p_l[o] = __float2half_rn(0.f); }
}

// ---------------------------------------------------------------------------
// mma.sync conv GEMM.
// CTA tile: 128 pixels (2 image rows) x 128 output channels. 8 warps (4x2),
// warp tile 32x64. K loop: 72 stages = 9 taps x 8 ci-chunks of 32.
// Per stage smem: Ah, Al (128x32 f16) + Bh, Bl (128x32 f16), rows padded to
// 80B (conflict-free ldmatrix). Double buffered with cp.async.
// Planes: acc += Ah*Bh + Ah*Bl + Al*Bh  (fp16 hi/lo split, err ~2^-24).
// ---------------------------------------------------------------------------
#define ROWB        80                       // bytes per smem row (64B data + 16B pad)
#define PLANE_B     (128 * ROWB)             // 10240
#define STAGE_B     (4 * PLANE_B)            // 40960
#define SMEM_TOTAL  (2 * STAGE_B)            // 81920
#define NSTAGES     72

template<int CONV>
__global__ void __launch_bounds__(256, 2)
conv_mma(const float* __restrict__ noise,
         const float* __restrict__ nscale,
         const float* __restrict__ bias,
         float* __restrict__ outp)
{
    constexpr int NTOT = CONV ? N2 : N1;
    extern __shared__ char smem[];
    const uint32_t sb = smem_to_u32(smem);

    const int tid  = threadIdx.x;
    const int lane = tid & 31;
    const int warp = tid >> 5;
    const int wm   = warp >> 1;          // 0..3  (32-row m slice)
    const int wn   = warp & 1;           // 0..1  (64-col n slice)

    const int mtile = blockIdx.y;        // 0..511
    const int b  = mtile >> 5;
    const int h0 = (mtile & 31) << 1;
    const int n0 = blockIdx.x << 7;

    const __half* __restrict__ Ahp = CONV ? g_x2p_h : g_xp_h;
    const __half* __restrict__ Alp = CONV ? g_x2p_l : g_xp_l;
    const __half* __restrict__ Whp = CONV ? g_w2h : g_w1h;
    const __half* __restrict__ Wlp = CONV ? g_w2l : g_w1l;

    // ---- producer task mapping: thread t loads rows r1 (=t>>2, h_off 0) and
    // r1+64 (h_off 1), 16B chunk c1 per row, for all 4 planes ----
    const int r1 = tid >> 2;             // 0..63
    const int c1 = tid & 3;              // 0..3

    // ldmatrix lane offsets (within a plane)
    uint32_t a_off[2], b_off[4];
    #pragma unroll
    for (int mf = 0; mf < 2; ++mf)
        a_off[mf] = (uint32_t)((wm * 32 + mf * 16 + (lane & 15)) * ROWB + (lane >> 4) * 16);
    #pragma unroll
    for (int nf = 0; nf < 4; ++nf)
        b_off[nf] = (uint32_t)((wn * 64 + nf * 16 + (lane & 7) + (lane >> 4) * 8) * ROWB
                               + ((lane >> 3) & 1) * 16);

    float acc[2][8][4];
    #pragma unroll
    for (int i = 0; i < 2; ++i)
        #pragma unroll
        for (int j = 0; j < 8; ++j)
            #pragma unroll
            for (int k = 0; k < 4; ++k) acc[i][j][k] = 0.f;

    auto load_stage = [&](int s, uint32_t buf) {
        const int tap = s >> 3;
        const int kc  = (s & 7) << 5;
        const int kh  = tap / 3, kw = tap % 3;
        // A: pixel rows (h0+kh, r1+kw) and (h0+1+kh, r1+kw)
        const size_t a1 = ((size_t)(b * PW + h0 + kh) * PW + (r1 + kw)) * CIN + kc + c1 * 8;
        const size_t a2 = a1 + (size_t)PW * CIN;
        const uint32_t d1 = buf + r1 * ROWB + c1 * 16;
        const uint32_t d2 = buf + (r1 + 64) * ROWB + c1 * 16;
        CPA16(d1,            Ahp + a1);  CPA16(d2,            Ahp + a2);
        CPA16(d1 + PLANE_B,  Alp + a1);  CPA16(d2 + PLANE_B,  Alp + a2);
        // B: weight rows n0+r1, n0+r1+64
        const size_t w1 = ((size_t)tap * NTOT + n0 + r1) * CIN + kc + c1 * 8;
        const size_t w2 = w1 + (size_t)64 * CIN;
        const uint32_t e1 = buf + 2 * PLANE_B + r1 * ROWB + c1 * 16;
        const uint32_t e2 = buf + 2 * PLANE_B + (r1 + 64) * ROWB + c1 * 16;
        CPA16(e1,            Whp + w1);  CPA16(e2,            Whp + w2);
        CPA16(e1 + PLANE_B,  Wlp + w1);  CPA16(e2 + PLANE_B,  Wlp + w2);
        CPA_COMMIT();
    };

    auto compute_stage = [&](uint32_t buf) {
        #pragma unroll
        for (int ks = 0; ks < 2; ++ks) {
            #pragma unroll
            for (int pp = 0; pp < 3; ++pp) {
                const uint32_t apl = buf + ((pp == 2) ? PLANE_B : 0u) + ks * 32;
                const uint32_t bpl = buf + ((pp == 1) ? 3u * PLANE_B : 2u * PLANE_B) + ks * 32;
                uint32_t a0[4], a1r[4];
                LDSM4(a0,  apl + a_off[0]);
                LDSM4(a1r, apl + a_off[1]);
                #pragma unroll
                for (int nf = 0; nf < 4; ++nf) {
                    uint32_t bf[4];
                    LDSM4(bf, bpl + b_off[nf]);
                    MMA16816(acc[0][nf * 2],     a0,  bf[0], bf[1]);
                    MMA16816(acc[0][nf * 2 + 1], a0,  bf[2], bf[3]);
                    MMA16816(acc[1][nf * 2],     a1r, bf[0], bf[1]);
                    MMA16816(acc[1][nf * 2 + 1], a1r, bf[2], bf[3]);
                }
            }
        }
    };

    // ---- pipelined main loop ----
    load_stage(0, sb);
    #pragma unroll 1
    for (int s = 0; s < NSTAGES; ++s) {
        if (s + 1 < NSTAGES) {
            load_stage(s + 1, sb + ((s + 1) & 1) * STAGE_B);
            CPA_WAIT_1();
        } else {
            CPA_WAIT_0();
        }
        __syncthreads();
        compute_stage(sb + (s & 1) * STAGE_B);
        __syncthreads();
    }

    // ---- epilogue ----
    const float ns = nscale[0];
    const float* __restrict__ dm = (CONV ? g_d2 : g_d1) + b * NTOT;
    const int q2 = (lane & 3) * 2;
    const int rr = lane >> 2;

    #pragma unroll
    for (int mf = 0; mf < 2; ++mf) {
        #pragma unroll
        for (int hf = 0; hf < 2; ++hf) {
            const int ml = wm * 32 + mf * 16 + rr + hf * 8;
            const int h  = h0 + (ml >> 6);
            const int w  = ml & 63;
            const float nz = noise[((size_t)b * H_SZ + h) * W_SZ + w] * ns;
            #pragma unroll
            for (int nf = 0; nf < 8; ++nf) {
                const int co = n0 + wn * 64 + nf * 8 + q2;
                float v0 = acc[mf][nf][hf * 2]     * dm[co]     + nz + bias[co];
                float v1 = acc[mf][nf][hf * 2 + 1] * dm[co + 1] + nz + bias[co + 1];
                v0 = (v0 > 0.f) ? v0 : 0.2f * v0;
                v1 = (v1 > 0.f) ? v1 : 0.2f * v1;
                if (CONV == 0) {
                    const float m0 = v0 * g_s2[b * CIN + co];
                    const float m1 = v1 * g_s2[b * CIN + co + 1];
                    const __half h0h = __float2half_rn(m0);
                    const __half h1h = __float2half_rn(m1);
                    const __half l0h = __float2half_rn(m0 - __half2float(h0h));
                    const __half l1h = __float2half_rn(m1 - __half2float(h1h));
                    const size_t o = ((size_t)(b * PW + h + 1) * PW + (w + 1)) * CIN + co;
                    *reinterpret_cast<__half2*>(g_x2p_h + o) = __halves2half2(h0h, h1h);
                    *reinterpret_cast<__half2*>(g_x2p_l + o) = __halves2half2(l0h, l1h);
                } else {
                    const int sh = co >> 8, sw = (co >> 7) & 1, c2 = co & 127;
                    float2 vv = make_float2(v0, v1);
                    *reinterpret_cast<float2*>(
                        outp + (((size_t)(b * 128 + 2 * h + sh)) * 128 + (2 * w + sw)) * 128 + c2) = vv;
                }
            }
        }
    }
}

// ---------------------------------------------------------------------------
// host
// ---------------------------------------------------------------------------
extern "C" void kernel_launch(void* const* d_in, const int* in_sizes, int n_in,
                              void* d_out, int out_size)
{
    const float* x    = (const float*)d_in[0];
    const float* w    = (const float*)d_in[1];
    const float* a1w  = (const float*)d_in[2];
    const float* a1b  = (const float*)d_in[3];
    const float* k1   = (const float*)d_in[4];
    const float* ns1  = (const float*)d_in[5];
    const float* b1   = (const float*)d_in[6];
    const float* a2w  = (const float*)d_in[7];
    const float* a2b  = (const float*)d_in[8];
    const float* k2   = (const float*)d_in[9];
    const float* ns2  = (const float*)d_in[10];
    const float* b2   = (const float*)d_in[11];
    const float* noi1 = (const float*)d_in[12];
    const float* noi2 = (const float*)d_in[13];
    float* outp = (float*)d_out;

    cudaFuncSetAttribute(conv_mma<0>, cudaFuncAttributeMaxDynamicSharedMemorySize, SMEM_TOTAL);
    cudaFuncSetAttribute(conv_mma<1>, cudaFuncAttributeMaxDynamicSharedMemorySize, SMEM_TOTAL);

    // prepare
    style_kernel<0><<<B_SZ, CIN>>>(w, a1w, a1b);
    style_kernel<1><<<B_SZ, CIN>>>(w, a2w, a2b);
    ksq_kernel<0, N1><<<(CIN * N1 + 255) / 256, 256>>>(k1);
    ksq_kernel<1, N2><<<(CIN * N2 + 255) / 256, 256>>>(k2);
    { dim3 g1(N1 / 256, B_SZ); demod_kernel<0, N1><<<g1, 256>>>(); }
    { dim3 g2(N2 / 256, B_SZ); demod_kernel<1, N2><<<g2, 256>>>(); }
    wsplit_kernel<0, N1><<<(9 * CIN * N1 + 255) / 256, 256>>>(k1);
    wsplit_kernel<1, N2><<<(9 * CIN * N2 + 255) / 256, 256>>>(k2);
    pad_kernel<<<B_SZ * PW * PW, 256>>>(x);

    // conv1: xpad -> x2pad (epilogue multiplies by s2 and splits to fp16)
    {
        dim3 grid(N1 / 128, 512);
        conv_mma<0><<<grid, 256, SMEM_TOTAL>>>(noi1, ns1, b1, nullptr);
    }
    // conv2: x2pad -> d_out (pixel shuffled)
    {
        dim3 grid(N2 / 128, 512);
        conv_mma<1><<<grid, 256, SMEM_TOTAL>>>(noi2, ns2, b2, outp);
    }
}

// round 4
// speedup vs baseline: 4.2362x; 1.0140x over previous
#include <cuda_runtime.h>
#include <cuda_fp16.h>
#include <cstdint>

// ---------------------------------------------------------------------------
// SynthesisBlock via mma.sync (HMMA) fp16 hi/lo 3-plane split GEMMs.
// R4: A-slab reused across 9 taps, M=256 CTA tile, fused prep kernels.
// ---------------------------------------------------------------------------
#define B_SZ 16
#define H_SZ 64
#define W_SZ 64
#define CIN  256
#define N1   256
#define N2   512
#define WDIM 128
#define PW   66          // padded H/W

// ---- device scratch ----
__device__ float g_s1[B_SZ * CIN];
__device__ float g_s2[B_SZ * CIN];
__device__ float g_d1[B_SZ * N1];
__device__ float g_d2[B_SZ * N2];
__device__ __half g_xp_h [B_SZ * PW * PW * CIN];   // conv1 input, modulated by s1, hi
__device__ __half g_xp_l [B_SZ * PW * PW * CIN];
__device__ __half g_x2p_h[B_SZ * PW * PW * CIN];   // conv2 input (h * s2), hi
__device__ __half g_x2p_l[B_SZ * PW * PW * CIN];
__device__ __half g_w1h[9 * N1 * CIN];             // [tap][n][ci]
__device__ __half g_w1l[9 * N1 * CIN];
__device__ __half g_w2h[9 * N2 * CIN];
__device__ __half g_w2l[9 * N2 * CIN];

// ---------------------------------------------------------------------------
// low-level helpers
// ---------------------------------------------------------------------------
__device__ __forceinline__ uint32_t smem_to_u32(const void* p) {
    uint32_t a;
    asm("{ .reg .u64 t; cvta.to.shared.u64 t, %1; cvt.u32.u64 %0, t; }" : "=r"(a) : "l"(p));
    return a;
}

#define CPA16(dst, src) \
    asm volatile("cp.async.cg.shared.global [%0], [%1], 16;" :: "r"(dst), "l"(src))
#define CPA_COMMIT() asm volatile("cp.async.commit_group;" ::: "memory")
#define CPA_WAIT_1() asm volatile("cp.async.wait_group 1;" ::: "memory")
#define CPA_WAIT_0() asm volatile("cp.async.wait_group 0;" ::: "memory")

#define LDSM4(r, addr) \
    asm volatile("ldmatrix.sync.aligned.m8n8.x4.shared.b16 {%0,%1,%2,%3}, [%4];" \
        : "=r"((r)[0]), "=r"((r)[1]), "=r"((r)[2]), "=r"((r)[3]) : "r"(addr))

#define MMA16816(d, a, b0_, b1_) \
    asm volatile("mma.sync.aligned.m16n8k16.row.col.f32.f16.f16.f32 " \
        "{%0,%1,%2,%3}, {%4,%5,%6,%7}, {%8,%9}, {%0,%1,%2,%3};" \
        : "+f"((d)[0]), "+f"((d)[1]), "+f"((d)[2]), "+f"((d)[3]) \
        : "r"((a)[0]), "r"((a)[1]), "r"((a)[2]), "r"((a)[3]), "r"(b0_), "r"(b1_))

// ---------------------------------------------------------------------------
// prep 1: styles (both convs in one launch)
// ---------------------------------------------------------------------------
__global__ void style_all(const float* __restrict__ w,
                          const float* __restrict__ a1w, const float* __restrict__ a1b,
                          const float* __restrict__ a2w, const float* __restrict__ a2b)
{
    int b = blockIdx.x, ci = threadIdx.x, which = blockIdx.y;
    const float* aw = which ? a2w : a1w;
    const float* ab = which ? a2b : a1b;
    float sum = ab[ci];
    const float* wr = w + b * WDIM;
    #pragma unroll 8
    for (int k = 0; k < WDIM; ++k) sum += wr[k] * aw[k * CIN + ci];
    (which ? g_s2 : g_s1)[b * CIN + ci] = sum;
}

// ---------------------------------------------------------------------------
// prep 2: demod (ksq fused; grid (6, B): x = co-chunk (0,1=conv1; 2..5=conv2))
// ---------------------------------------------------------------------------
__global__ void demod_all(const float* __restrict__ k1, const float* __restrict__ k2)
{
    const int blkx = blockIdx.x;
    const int conv = (blkx >= 2);
    const int NT   = conv ? N2 : N1;
    const int co   = (conv ? (blkx - 2) : blkx) * 128 + threadIdx.x;
    const int b    = blockIdx.y;
    const float* kern = conv ? k2 : k1;
    const float* st   = conv ? g_s2 : g_s1;

    __shared__ float ssq[CIN];
    for (int i = threadIdx.x; i < CIN; i += 128) {
        float s = st[b * CIN + i];
        ssq[i] = s * s;
    }
    __syncthreads();

    float acc = 0.f;
    for (int ci = 0; ci < CIN; ++ci) {
        float kv = 0.f;
        #pragma unroll
        for (int p = 0; p < 9; ++p) {
            float v = kern[((size_t)p * CIN + ci) * NT + co];
            kv += v * v;
        }
        acc += ssq[ci] * kv;
    }
    (conv ? g_d2 : g_d1)[b * NT + co] = rsqrtf(acc + 1e-8f);
}

// ---------------------------------------------------------------------------
// prep 3: weight transpose + fp16 hi/lo split (both convs; grid.y selects)
// ---------------------------------------------------------------------------
__global__ void wsplit_all(const float* __restrict__ k1, const float* __restrict__ k2)
{
    const int conv = blockIdx.y;
    const int NT   = conv ? N2 : N1;
    int idx = blockIdx.x * blockDim.x + threadIdx.x;
    if (idx >= 9 * CIN * NT) return;
    int tap = idx / (CIN * NT);
    int r   = idx % (CIN * NT);
    int ci  = r / NT;
    int n   = r % NT;
    float v = (conv ? k2 : k1)[idx];
    __half hi = __float2half_rn(v);
    __half lo = __float2half_rn(v - __half2float(hi));
    size_t o = ((size_t)tap * NT + n) * CIN + ci;
    if (conv == 0) { g_w1h[o] = hi; g_w1l[o] = lo; }
    else           { g_w2h[o] = hi; g_w2l[o] = lo; }
}

// ---------------------------------------------------------------------------
// prep 4: pad + modulate-by-s1 + fp16 split; zero x2pad borders too
// ---------------------------------------------------------------------------
__global__ void pad_kernel(const float* __restrict__ x)
{
    int pix = blockIdx.x;                 // 0 .. B*PW*PW-1
    int b  = pix / (PW * PW);
    int r  = pix % (PW * PW);
    int hp = r / PW, wp = r % PW;
    int ci = threadIdx.x;
    bool interior = (hp >= 1) && (hp <= H_SZ) && (wp >= 1) && (wp <= W_SZ);
    float v = 0.f;
    if (interior)
        v = x[(((size_t)b * H_SZ + (hp - 1)) * W_SZ + (wp - 1)) * CIN + ci] * g_s1[b * CIN + ci];
    __half hi = __float2half_rn(v);
    __half lo = __float2half_rn(v - __half2float(hi));
    size_t o = (size_t)pix * CIN + ci;
    g_xp_h[o] = hi; g_xp_l[o] = lo;
    if (!interior) { g_x2p_h[o] = __float2half_rn(0.f); g_x2p_l[o] = __float2half_rn(0.f); }
}

// ---------------------------------------------------------------------------
// conv GEMM. CTA: 256 pixels (4 image rows) x 128 output channels.
// 512 threads, 16 warps (8m x 2n), warp tile 32x64.
// Outer loop: 8 ci-chunks of 32; A slab (6 padded rows x 66 px, 2 planes)
// loaded once per chunk, reused by all 9 taps via smem row offset.
// Inner loop: 9 taps; weights (128 x 32, 2 planes) streamed per tap.
// MMA passes per tap-stage: Ah*Wh + Al*Wh + Ah*Wl  (3-plane fp16 split).
// ---------------------------------------------------------------------------
#define ROWB      80                      // 64B data + 16B pad per pixel-row
#define A_PLANE_B (396 * ROWB)            // 31680
#define A_BUF_B   (2 * A_PLANE_B)         // 63360 (hi+lo)
#define W_PLANE_B (128 * ROWB)            // 10240
#define W_BUF_B   (2 * W_PLANE_B)         // 20480
#define SMEM_W0   (2 * A_BUF_B)           // 126720
#define SMEM_TOTAL (2 * A_BUF_B + 2 * W_BUF_B)   // 167680

template<int CONV>
__global__ void __launch_bounds__(512, 1)
conv_mma(const float* __restrict__ noise,
         const float* __restrict__ nscale,
         const float* __restrict__ bias,
         float* __restrict__ outp)
{
    constexpr int NTOT = CONV ? N2 : N1;
    extern __shared__ char smem[];
    const uint32_t sb = smem_to_u32(smem);

    const int tid  = threadIdx.x;
    const int lane = tid & 31;
    const int warp = tid >> 5;
    const int wm   = warp >> 1;          // 0..7  (32-row m slice)
    const int wn   = warp & 1;           // 0..1  (64-col n slice)

    const int mtile = blockIdx.y;        // 0..255
    const int b  = mtile >> 4;
    const int R  = (mtile & 15) << 2;    // first output image row (4 rows per CTA)
    const int n0 = blockIdx.x << 7;

    const __half* __restrict__ Ah_p = CONV ? g_x2p_h : g_xp_h;
    const __half* __restrict__ Al_p = CONV ? g_x2p_l : g_xp_l;
    const __half* __restrict__ Wh_p = CONV ? g_w2h : g_w1h;
    const __half* __restrict__ Wl_p = CONV ? g_w2l : g_w1l;

    // ---- ldmatrix fragment smem offsets ----
    uint32_t a_base[2];
    #pragma unroll
    for (int mf = 0; mf < 2; ++mf) {
        const int m    = wm * 32 + mf * 16 + (lane & 15);
        const int srow = (m >> 6) * 66 + (m & 63);     // slab pixel-row (tap 0)
        a_base[mf] = (uint32_t)(srow * ROWB + ((lane >> 4) << 4));
    }
    uint32_t b_off[4];
    #pragma unroll
    for (int nf = 0; nf < 4; ++nf)
        b_off[nf] = (uint32_t)((wn * 64 + nf * 16 + (lane & 7) + ((lane >> 4) << 3)) * ROWB
                               + (((lane >> 3) & 1) << 4));

    float acc[2][8][4];
    #pragma unroll
    for (int i = 0; i < 2; ++i)
        #pragma unroll
        for (int j = 0; j < 8; ++j)
            #pragma unroll
            for (int k = 0; k < 4; ++k) acc[i][j][k] = 0.f;

    // ---- producer helpers ----
    // W tile (tap, chunk): 128 rows x 32ci x 2 planes = 1024 CPA16 (2/thread)
    auto loadW = [&](int tap, int c, uint32_t buf) {
        #pragma unroll
        for (int k = 0; k < 2; ++k) {
            const int idx   = tid + k * 512;
            const int row   = idx >> 3;
            const int plane = (idx >> 2) & 1;
            const int c16   = idx & 3;
            const __half* src = (plane ? Wl_p : Wh_p)
                + ((size_t)(tap * NTOT + n0 + row)) * CIN + c * 32 + c16 * 8;
            CPA16(buf + plane * W_PLANE_B + row * ROWB + c16 * 16, src);
        }
    };

    // ---- prologue: full A slab chunk 0 + W(tap0, chunk0) ----
    {
        #pragma unroll
        for (int it = 0; it < 7; ++it) {
            const int idx = it * 512 + tid;
            if (idx < 3168) {                       // 396 rows * 8
                const int row   = idx >> 3;
                const int plane = (idx >> 2) & 1;
                const int c16   = idx & 3;
                const int i = row / 66, j = row - i * 66;
                const __half* src = (plane ? Al_p : Ah_p)
                    + ((size_t)((b * PW + R + i)) * PW + j) * CIN + c16 * 8;
                CPA16(sb + plane * A_PLANE_B + row * ROWB + c16 * 16, src);
            }
        }
        loadW(0, 0, sb + SMEM_W0);
        CPA_COMMIT();
    }

    // ---- main loop: 8 chunks x 9 taps ----
    int s = 0;
    #pragma unroll 1
    for (int c = 0; c < 8; ++c) {
        const uint32_t Ab = sb + (c & 1) * A_BUF_B;
        #pragma unroll 1
        for (int t = 0; t < 9; ++t, ++s) {
            if (s < 71) {
                const int nc = (t == 8) ? c + 1 : c;
                const int nt = (t == 8) ? 0 : t + 1;
                loadW(nt, nc, sb + SMEM_W0 + ((s + 1) & 1) * W_BUF_B);
                if (c < 7 && tid < 352) {           // A slice t of chunk c+1 (44 rows)
                    const int row   = 44 * t + (tid >> 3);
                    const int plane = (tid >> 2) & 1;
                    const int c16   = tid & 3;
                    const int i = row / 66, j = row - i * 66;
                    const __half* src = (plane ? Al_p : Ah_p)
                        + ((size_t)((b * PW + R + i)) * PW + j) * CIN + (c + 1) * 32 + c16 * 8;
                    CPA16(sb + ((c + 1) & 1) * A_BUF_B + plane * A_PLANE_B
                          + row * ROWB + c16 * 16, src);
                }
                CPA_COMMIT();
                CPA_WAIT_1();
            } else {
                CPA_WAIT_0();
            }
            __syncthreads();

            // ---- compute tap t on chunk c ----
            const uint32_t Wb   = sb + SMEM_W0 + (s & 1) * W_BUF_B;
            const uint32_t Aofs = (uint32_t)(((t / 3) * 66 + (t % 3)) * ROWB);
            #pragma unroll
            for (int ks = 0; ks < 2; ++ks) {
                uint32_t ah0[4], ah1[4], al0[4], al1[4];
                LDSM4(ah0, Ab + Aofs + a_base[0] + ks * 32);
                LDSM4(ah1, Ab + Aofs + a_base[1] + ks * 32);
                LDSM4(al0, Ab + A_PLANE_B + Aofs + a_base[0] + ks * 32);
                LDSM4(al1, Ab + A_PLANE_B + Aofs + a_base[1] + ks * 32);
                #pragma unroll
                for (int nf = 0; nf < 4; ++nf) {
                    uint32_t bh[4], bl[4];
                    LDSM4(bh, Wb + b_off[nf] + ks * 32);
                    MMA16816(acc[0][nf * 2],     ah0, bh[0], bh[1]);
                    MMA16816(acc[0][nf * 2 + 1], ah0, bh[2], bh[3]);
                    MMA16816(acc[1][nf * 2],     ah1, bh[0], bh[1]);
                    MMA16816(acc[1][nf * 2 + 1], ah1, bh[2], bh[3]);
                    MMA16816(acc[0][nf * 2],     al0, bh[0], bh[1]);
                    MMA16816(acc[0][nf * 2 + 1], al0, bh[2], bh[3]);
                    MMA16816(acc[1][nf * 2],     al1, bh[0], bh[1]);
                    MMA16816(acc[1][nf * 2 + 1], al1, bh[2], bh[3]);
                    LDSM4(bl, Wb + W_PLANE_B + b_off[nf] + ks * 32);
                    MMA16816(acc[0][nf * 2],     ah0, bl[0], bl[1]);
                    MMA16816(acc[0][nf * 2 + 1], ah0, bl[2], bl[3]);
                    MMA16816(acc[1][nf * 2],     ah1, bl[0], bl[1]);
                    MMA16816(acc[1][nf * 2 + 1], ah1, bl[2], bl[3]);
                }
            }
            __syncthreads();
        }
    }

    // ---- epilogue ----
    const float ns = nscale[0];
    const float* __restrict__ dm = (CONV ? g_d2 : g_d1) + b * NTOT;
    const int q2 = (lane & 3) * 2;
    const int rr = lane >> 2;

    #pragma unroll
    for (int mf = 0; mf < 2; ++mf) {
        #pragma unroll
        for (int hf = 0; hf < 2; ++hf) {
            const int ml = wm * 32 + mf * 16 + rr + hf * 8;    // 0..255
            const int h  = R + (ml >> 6);
            const int w  = ml & 63;
            const float nz = noise[((size_t)b * H_SZ + h) * W_SZ + w] * ns;
            #pragma unroll
            for (int nf = 0; nf < 8; ++nf) {
                const int co = n0 + wn * 64 + nf * 8 + q2;
                float v0 = acc[mf][nf][hf * 2]     * dm[co]     + nz + bias[co];
                float v1 = acc[mf][nf][hf * 2 + 1] * dm[co + 1] + nz + bias[co + 1];
                v0 = (v0 > 0.f) ? v0 : 0.2f * v0;
                v1 = (v1 > 0.f) ? v1 : 0.2f * v1;
                if (CONV == 0) {
                    const float m0 = v0 * g_s2[b * CIN + co];
                    const float m1 = v1 * g_s2[b * CIN + co + 1];
                    const __half h0h = __float2half_rn(m0);
                    const __half h1h = __float2half_rn(m1);
                    const __half l0h = __float2half_rn(m0 - __half2float(h0h));
                    const __half l1h = __float2half_rn(m1 - __half2float(h1h));
                    const size_t o = ((size_t)(b * PW + h + 1) * PW + (w + 1)) * CIN + co;
                    *reinterpret_cast<__half2*>(g_x2p_h + o) = __halves2half2(h0h, h1h);
                    *reinterpret_cast<__half2*>(g_x2p_l + o) = __halves2half2(l0h, l1h);
                } else {
                    const int sh = co >> 8, sw = (co >> 7) & 1, c2 = co & 127;
                    float2 vv = make_float2(v0, v1);
                    *reinterpret_cast<float2*>(
                        outp + (((size_t)(b * 128 + 2 * h + sh)) * 128 + (2 * w + sw)) * 128 + c2) = vv;
                }
            }
        }
    }
}

// ---------------------------------------------------------------------------
// host
// ---------------------------------------------------------------------------
extern "C" void kernel_launch(void* const* d_in, const int* in_sizes, int n_in,
                              void* d_out, int out_size)
{
    const float* x    = (const float*)d_in[0];
    const float* w    = (const float*)d_in[1];
    const float* a1w  = (const float*)d_in[2];
    const float* a1b  = (const float*)d_in[3];
    const float* k1   = (const float*)d_in[4];
    const float* ns1  = (const float*)d_in[5];
    const float* b1   = (const float*)d_in[6];
    const float* a2w  = (const float*)d_in[7];
    const float* a2b  = (const float*)d_in[8];
    const float* k2   = (const float*)d_in[9];
    const float* ns2  = (const float*)d_in[10];
    const float* b2   = (const float*)d_in[11];
    const float* noi1 = (const float*)d_in[12];
    const float* noi2 = (const float*)d_in[13];
    float* outp = (float*)d_out;

    cudaFuncSetAttribute(conv_mma<0>, cudaFuncAttributeMaxDynamicSharedMemorySize, SMEM_TOTAL);
    cudaFuncSetAttribute(conv_mma<1>, cudaFuncAttributeMaxDynamicSharedMemorySize, SMEM_TOTAL);

    // prep (4 launches so ncu -s 5 lands on conv2)
    { dim3 g(B_SZ, 2);  style_all<<<g, CIN>>>(w, a1w, a1b, a2w, a2b); }
    { dim3 g(6, B_SZ);  demod_all<<<g, 128>>>(k1, k2); }
    { dim3 g((9 * CIN * N2 + 255) / 256, 2); wsplit_all<<<g, 256>>>(k1, k2); }
    pad_kernel<<<B_SZ * PW * PW, 256>>>(x);

    // conv1: xpad -> x2pad (epilogue multiplies by s2 and splits to fp16)
    {
        dim3 grid(N1 / 128, 256);
        conv_mma<0><<<grid, 512, SMEM_TOTAL>>>(noi1, ns1, b1, nullptr);
    }
    // conv2: x2pad -> d_out (pixel shuffled)
    {
        dim3 grid(N2 / 128, 256);
        conv_mma<1><<<grid, 512, SMEM_TOTAL>>>(noi2, ns2, b2, outp);
    }
}

// round 5
// speedup vs baseline: 5.9488x; 1.4043x over previous
#include <cuda_runtime.h>
#include <cuda_fp16.h>
#include <cstdint>

// ---------------------------------------------------------------------------
// SynthesisBlock via mma.sync (HMMA).
// R5: A single fp16 plane, W fp16 hi/lo split -> 2 MMA passes (err ~2^-12),
//     M=128 CTA, 256 thr, 83KB smem -> 2 CTAs/SM. A-slab reused across taps.
// ---------------------------------------------------------------------------
#define B_SZ 16
#define H_SZ 64
#define W_SZ 64
#define CIN  256
#define N1   256
#define N2   512
#define WDIM 128
#define PW   66          // padded H/W

// ---- device scratch ----
__device__ float g_s1[B_SZ * CIN];
__device__ float g_s2[B_SZ * CIN];
__device__ float g_d1[B_SZ * N1];
__device__ float g_d2[B_SZ * N2];
__device__ __half g_xp [B_SZ * PW * PW * CIN];     // conv1 input, modulated by s1
__device__ __half g_x2p[B_SZ * PW * PW * CIN];     // conv2 input (h * s2)
__device__ __half g_w1h[9 * N1 * CIN];             // [tap][n][ci]
__device__ __half g_w1l[9 * N1 * CIN];
__device__ __half g_w2h[9 * N2 * CIN];
__device__ __half g_w2l[9 * N2 * CIN];

// ---------------------------------------------------------------------------
// low-level helpers
// ---------------------------------------------------------------------------
__device__ __forceinline__ uint32_t smem_to_u32(const void* p) {
    uint32_t a;
    asm("{ .reg .u64 t; cvta.to.shared.u64 t, %1; cvt.u32.u64 %0, t; }" : "=r"(a) : "l"(p));
    return a;
}

#define CPA16(dst, src) \
    asm volatile("cp.async.cg.shared.global [%0], [%1], 16;" :: "r"(dst), "l"(src))
#define CPA_COMMIT() asm volatile("cp.async.commit_group;" ::: "memory")
#define CPA_WAIT_1() asm volatile("cp.async.wait_group 1;" ::: "memory")
#define CPA_WAIT_0() asm volatile("cp.async.wait_group 0;" ::: "memory")

#define LDSM4(r, addr) \
    asm volatile("ldmatrix.sync.aligned.m8n8.x4.shared.b16 {%0,%1,%2,%3}, [%4];" \
        : "=r"((r)[0]), "=r"((r)[1]), "=r"((r)[2]), "=r"((r)[3]) : "r"(addr))

#define MMA16816(d, a, b0_, b1_) \
    asm volatile("mma.sync.aligned.m16n8k16.row.col.f32.f16.f16.f32 " \
        "{%0,%1,%2,%3}, {%4,%5,%6,%7}, {%8,%9}, {%0,%1,%2,%3};" \
        : "+f"((d)[0]), "+f"((d)[1]), "+f"((d)[2]), "+f"((d)[3]) \
        : "r"((a)[0]), "r"((a)[1]), "r"((a)[2]), "r"((a)[3]), "r"(b0_), "r"(b1_))

// ---------------------------------------------------------------------------
// prep 1: styles
// ---------------------------------------------------------------------------
__global__ void style_all(const float* __restrict__ w,
                          const float* __restrict__ a1w, const float* __restrict__ a1b,
                          const float* __restrict__ a2w, const float* __restrict__ a2b)
{
    int b = blockIdx.x, ci = threadIdx.x, which = blockIdx.y;
    const float* aw = which ? a2w : a1w;
    const float* ab = which ? a2b : a1b;
    float sum = ab[ci];
    const float* wr = w + b * WDIM;
    #pragma unroll 8
    for (int k = 0; k < WDIM; ++k) sum += wr[k] * aw[k * CIN + ci];
    (which ? g_s2 : g_s1)[b * CIN + ci] = sum;
}

// ---------------------------------------------------------------------------
// prep 2: demod (ksq fused)
// ---------------------------------------------------------------------------
__global__ void demod_all(const float* __restrict__ k1, const float* __restrict__ k2)
{
    const int blkx = blockIdx.x;
    const int conv = (blkx >= 2);
    const int NT   = conv ? N2 : N1;
    const int co   = (conv ? (blkx - 2) : blkx) * 128 + threadIdx.x;
    const int b    = blockIdx.y;
    const float* kern = conv ? k2 : k1;
    const float* st   = conv ? g_s2 : g_s1;

    __shared__ float ssq[CIN];
    for (int i = threadIdx.x; i < CIN; i += 128) {
        float s = st[b * CIN + i];
        ssq[i] = s * s;
    }
    __syncthreads();

    float acc = 0.f;
    for (int ci = 0; ci < CIN; ++ci) {
        float kv = 0.f;
        #pragma unroll
        for (int p = 0; p < 9; ++p) {
            float v = kern[((size_t)p * CIN + ci) * NT + co];
            kv += v * v;
        }
        acc += ssq[ci] * kv;
    }
    (conv ? g_d2 : g_d1)[b * NT + co] = rsqrtf(acc + 1e-8f);
}

// ---------------------------------------------------------------------------
// prep 3: weight transpose + fp16 hi/lo split: out[tap][n][ci]
// ---------------------------------------------------------------------------
__global__ void wsplit_all(const float* __restrict__ k1, const float* __restrict__ k2)
{
    const int conv = blockIdx.y;
    const int NT   = conv ? N2 : N1;
    int idx = blockIdx.x * blockDim.x + threadIdx.x;
    if (idx >= 9 * CIN * NT) return;
    int tap = idx / (CIN * NT);
    int r   = idx % (CIN * NT);
    int ci  = r / NT;
    int n   = r % NT;
    float v = (conv ? k2 : k1)[idx];
    __half hi = __float2half_rn(v);
    __half lo = __float2half_rn(v - __half2float(hi));
    size_t o = ((size_t)tap * NT + n) * CIN + ci;
    if (conv == 0) { g_w1h[o] = hi; g_w1l[o] = lo; }
    else           { g_w2h[o] = hi; g_w2l[o] = lo; }
}

// ---------------------------------------------------------------------------
// prep 4: pad + modulate-by-s1 -> single fp16 plane; zero x2p borders.
// 256 thr = 4 pixels x 64 thread-groups of 4 ci.
// ---------------------------------------------------------------------------
__global__ void pad_kernel(const float* __restrict__ x)
{
    const int tid = threadIdx.x;
    const int pix = blockIdx.x * 4 + (tid >> 6);     // 0 .. B*PW*PW-1
    const int ci  = (tid & 63) << 2;
    const int b  = pix / (PW * PW);
    const int r  = pix % (PW * PW);
    const int hp = r / PW, wp = r % PW;
    const bool interior = (hp >= 1) && (hp <= H_SZ) && (wp >= 1) && (wp <= W_SZ);

    uint2 packed = make_uint2(0u, 0u);
    if (interior) {
        const float4 v = *reinterpret_cast<const float4*>(
            x + (((size_t)b * H_SZ + (hp - 1)) * W_SZ + (wp - 1)) * CIN + ci);
        const float4 s = *reinterpret_cast<const float4*>(g_s1 + b * CIN + ci);
        __half2 p0 = __halves2half2(__float2half_rn(v.x * s.x), __float2half_rn(v.y * s.y));
        __half2 p1 = __halves2half2(__float2half_rn(v.z * s.z), __float2half_rn(v.w * s.w));
        packed.x = *reinterpret_cast<uint32_t*>(&p0);
        packed.y = *reinterpret_cast<uint32_t*>(&p1);
    }
    const size_t o = (size_t)pix * CIN + ci;
    *reinterpret_cast<uint2*>(g_xp + o) = packed;
    if (!interior)
        *reinterpret_cast<uint2*>(g_x2p + o) = make_uint2(0u, 0u);
}

// ---------------------------------------------------------------------------
// conv GEMM. CTA: 128 pixels (2 image rows) x 128 output channels.
// 256 threads, 8 warps (4m x 2n), warp tile 32x64.
// Outer: 8 ci-chunks of 32; A slab (4 padded rows x 66 px, single plane)
// double-buffered, loaded incrementally, reused by all 9 taps.
// Inner: 9 taps; W (128 x 32, hi+lo) ping-pong per tap.
// MMA passes per tap: A*Wh + A*Wl.
// ---------------------------------------------------------------------------
#define ROWB       80                     // 64B data + 16B pad per pixel-row
#define A_PLANE_B  (264 * ROWB)           // 21120
#define W_PLANE_B  (128 * ROWB)           // 10240
#define W_BUF_B    (2 * W_PLANE_B)        // 20480 (hi+lo)
#define SMEM_W0    (2 * A_PLANE_B)        // 42240
#define SMEM_TOTAL (2 * A_PLANE_B + 2 * W_BUF_B)   // 83200

template<int CONV>
__global__ void __launch_bounds__(256, 2)
conv_mma(const float* __restrict__ noise,
         const float* __restrict__ nscale,
         const float* __restrict__ bias,
         float* __restrict__ outp)
{
    constexpr int NTOT = CONV ? N2 : N1;
    extern __shared__ char smem[];
    const uint32_t sb = smem_to_u32(smem);

    const int tid  = threadIdx.x;
    const int lane = tid & 31;
    const int warp = tid >> 5;
    const int wm   = warp >> 1;          // 0..3  (32-row m slice)
    const int wn   = warp & 1;           // 0..1  (64-col n slice)

    const int mtile = blockIdx.y;        // 0..511
    const int b  = mtile >> 5;
    const int R  = (mtile & 31) << 1;    // first output image row (2 rows per CTA)
    const int n0 = blockIdx.x << 7;

    const __half* __restrict__ A_p  = CONV ? g_x2p : g_xp;
    const __half* __restrict__ Wh_p = CONV ? g_w2h : g_w1h;
    const __half* __restrict__ Wl_p = CONV ? g_w2l : g_w1l;

    // ---- ldmatrix fragment smem offsets ----
    uint32_t a_base[2];
    #pragma unroll
    for (int mf = 0; mf < 2; ++mf) {
        const int m    = wm * 32 + mf * 16 + (lane & 15);
        const int srow = (m >> 6) * 66 + (m & 63);      // slab pixel-row (tap 0)
        a_base[mf] = (uint32_t)(srow * ROWB + ((lane >> 4) << 4));
    }
    uint32_t b_off[4];
    #pragma unroll
    for (int nf = 0; nf < 4; ++nf)
        b_off[nf] = (uint32_t)((wn * 64 + nf * 16 + (lane & 7) + ((lane >> 4) << 3)) * ROWB
                               + (((lane >> 3) & 1) << 4));

    float acc[2][8][4];
    #pragma unroll
    for (int i = 0; i < 2; ++i)
        #pragma unroll
        for (int j = 0; j < 8; ++j)
            #pragma unroll
            for (int k = 0; k < 4; ++k) acc[i][j][k] = 0.f;

    // W tile (tap, chunk): 128 rows x 32ci x 2 planes = 1024 CPA16 (4/thread)
    auto loadW = [&](int tap, int c, uint32_t buf) {
        #pragma unroll
        for (int k = 0; k < 4; ++k) {
            const int idx   = tid + k * 256;
            const int row   = idx >> 3;
            const int plane = (idx >> 2) & 1;
            const int c16   = idx & 3;
            const __half* src = (plane ? Wl_p : Wh_p)
                + ((size_t)(tap * NTOT + n0 + row)) * CIN + c * 32 + c16 * 8;
            CPA16(buf + plane * W_PLANE_B + row * ROWB + c16 * 16, src);
        }
    };

    // ---- prologue: A slab chunk 0 (264 rows x 4 x 16B = 1056) + W(0,0) ----
    {
        #pragma unroll
        for (int it = 0; it < 5; ++it) {
            const int idx = it * 256 + tid;
            if (idx < 1056) {
                const int row = idx >> 2;
                const int c16 = idx & 3;
                const int i = row / 66, j = row - i * 66;
                const __half* src = A_p
                    + ((size_t)((b * PW + R + i)) * PW + j) * CIN + c16 * 8;
                CPA16(sb + row * ROWB + c16 * 16, src);
            }
        }
        loadW(0, 0, sb + SMEM_W0);
        CPA_COMMIT();
    }

    // ---- main loop: 8 chunks x 9 taps ----
    int s = 0;
    #pragma unroll 1
    for (int c = 0; c < 8; ++c) {
        const uint32_t Ab = sb + (c & 1) * A_PLANE_B;
        #pragma unroll 1
        for (int t = 0; t < 9; ++t, ++s) {
            if (s < 71) {
                const int nc = (t == 8) ? c + 1 : c;
                const int nt = (t == 8) ? 0 : t + 1;
                loadW(nt, nc, sb + SMEM_W0 + ((s + 1) & 1) * W_BUF_B);
                if (c < 7 && t < 8 && tid < 132) {  // A slice t of chunk c+1: 33 rows
                    const int row = 33 * t + (tid >> 2);
                    const int c16 = tid & 3;
                    const int i = row / 66, j = row - i * 66;
                    const __half* src = A_p
                        + ((size_t)((b * PW + R + i)) * PW + j) * CIN + (c + 1) * 32 + c16 * 8;
                    CPA16(sb + ((c + 1) & 1) * A_PLANE_B + row * ROWB + c16 * 16, src);
                }
                CPA_COMMIT();
                CPA_WAIT_1();
            } else {
                CPA_WAIT_0();
            }
            __syncthreads();

            // ---- compute tap t on chunk c ----
            const uint32_t Wb   = sb + SMEM_W0 + (s & 1) * W_BUF_B;
            const uint32_t Aofs = (uint32_t)(((t / 3) * 66 + (t % 3)) * ROWB);
            #pragma unroll
            for (int ks = 0; ks < 2; ++ks) {
                uint32_t a0[4], a1r[4];
                LDSM4(a0,  Ab + Aofs + a_base[0] + ks * 32);
                LDSM4(a1r, Ab + Aofs + a_base[1] + ks * 32);
                #pragma unroll
                for (int nf = 0; nf < 4; ++nf) {
                    uint32_t bh[4], bl[4];
                    LDSM4(bh, Wb + b_off[nf] + ks * 32);
                    MMA16816(acc[0][nf * 2],     a0,  bh[0], bh[1]);
                    MMA16816(acc[0][nf * 2 + 1], a0,  bh[2], bh[3]);
                    MMA16816(acc[1][nf * 2],     a1r, bh[0], bh[1]);
                    MMA16816(acc[1][nf * 2 + 1], a1r, bh[2], bh[3]);
                    LDSM4(bl, Wb + W_PLANE_B + b_off[nf] + ks * 32);
                    MMA16816(acc[0][nf * 2],     a0,  bl[0], bl[1]);
                    MMA16816(acc[0][nf * 2 + 1], a0,  bl[2], bl[3]);
                    MMA16816(acc[1][nf * 2],     a1r, bl[0], bl[1]);
                    MMA16816(acc[1][nf * 2 + 1], a1r, bl[2], bl[3]);
                }
            }
            __syncthreads();
        }
    }

    // ---- epilogue ----
    const float ns = nscale[0];
    const float* __restrict__ dm = (CONV ? g_d2 : g_d1) + b * NTOT;
    const int q2 = (lane & 3) * 2;
    const int rr = lane >> 2;

    #pragma unroll
    for (int mf = 0; mf < 2; ++mf) {
        #pragma unroll
        for (int hf = 0; hf < 2; ++hf) {
            const int ml = wm * 32 + mf * 16 + rr + hf * 8;    // 0..127
            const int h  = R + (ml >> 6);
            const int w  = ml & 63;
            const float nz = noise[((size_t)b * H_SZ + h) * W_SZ + w] * ns;
            #pragma unroll
            for (int nf = 0; nf < 8; ++nf) {
                const int co = n0 + wn * 64 + nf * 8 + q2;
                float v0 = acc[mf][nf][hf * 2]     * dm[co]     + nz + bias[co];
                float v1 = acc[mf][nf][hf * 2 + 1] * dm[co + 1] + nz + bias[co + 1];
                v0 = (v0 > 0.f) ? v0 : 0.2f * v0;
                v1 = (v1 > 0.f) ? v1 : 0.2f * v1;
                if (CONV == 0) {
                    const float m0 = v0 * g_s2[b * CIN + co];
                    const float m1 = v1 * g_s2[b * CIN + co + 1];
                    const size_t o = ((size_t)(b * PW + h + 1) * PW + (w + 1)) * CIN + co;
                    *reinterpret_cast<__half2*>(g_x2p + o) =
                        __halves2half2(__float2half_rn(m0), __float2half_rn(m1));
                } else {
                    const int sh = co >> 8, sw = (co >> 7) & 1, c2 = co & 127;
                    float2 vv = make_float2(v0, v1);
                    *reinterpret_cast<float2*>(
                        outp + (((size_t)(b * 128 + 2 * h + sh)) * 128 + (2 * w + sw)) * 128 + c2) = vv;
                }
            }
        }
    }
}

// ---------------------------------------------------------------------------
// host
// ---------------------------------------------------------------------------
extern "C" void kernel_launch(void* const* d_in, const int* in_sizes, int n_in,
                              void* d_out, int out_size)
{
    const float* x    = (const float*)d_in[0];
    const float* w    = (const float*)d_in[1];
    const float* a1w  = (const float*)d_in[2];
    const float* a1b  = (const float*)d_in[3];
    const float* k1   = (const float*)d_in[4];
    const float* ns1  = (const float*)d_in[5];
    const float* b1   = (const float*)d_in[6];
    const float* a2w  = (const float*)d_in[7];
    const float* a2b  = (const float*)d_in[8];
    const float* k2   = (const float*)d_in[9];
    const float* ns2  = (const float*)d_in[10];
    const float* b2   = (const float*)d_in[11];
    const float* noi1 = (const float*)d_in[12];
    const float* noi2 = (const float*)d_in[13];
    float* outp = (float*)d_out;

    cudaFuncSetAttribute(conv_mma<0>, cudaFuncAttributeMaxDynamicSharedMemorySize, SMEM_TOTAL);
    cudaFuncSetAttribute(conv_mma<1>, cudaFuncAttributeMaxDynamicSharedMemorySize, SMEM_TOTAL);

    // prep
    { dim3 g(B_SZ, 2);  style_all<<<g, CIN>>>(w, a1w, a1b, a2w, a2b); }
    { dim3 g(6, B_SZ);  demod_all<<<g, 128>>>(k1, k2); }
    { dim3 g((9 * CIN * N2 + 255) / 256, 2); wsplit_all<<<g, 256>>>(k1, k2); }
    pad_kernel<<<B_SZ * PW * PW / 4, 256>>>(x);

    // conv1: xp -> x2p (epilogue multiplies by s2, single fp16 plane)
    {
        dim3 grid(N1 / 128, 512);
        conv_mma<0><<<grid, 256, SMEM_TOTAL>>>(noi1, ns1, b1, nullptr);
    }
    // conv2: x2p -> d_out (pixel shuffled)
    {
        dim3 grid(N2 / 128, 512);
        conv_mma<1><<<grid, 256, SMEM_TOTAL>>>(noi2, ns2, b2, outp);
    }
}

// round 7
// speedup vs baseline: 7.1585x; 1.2034x over previous
#include <cuda_runtime.h>
#include <cuda.h>
#include <cuda_fp16.h>
#include <cstdint>

// ---------------------------------------------------------------------------
// SynthesisBlock via mma.sync (HMMA), TMA bulk-tensor producers.
// R7 = R6 with 128B-aligned TMA smem destinations (A slab split 136+136 rows,
// second box at +10880 which is 85*128). Math identical to R5/R6:
// A single fp16 plane, W fp16 hi/lo split -> 2 MMA passes.
// ---------------------------------------------------------------------------
#define B_SZ 16
#define H_SZ 64
#define W_SZ 64
#define CIN  256
#define N1   256
#define N2   512
#define WDIM 128
#define PW   66          // padded H/W
#define NPIX (B_SZ * PW * PW)

// ---- device scratch ----
__device__ float g_s1[B_SZ * CIN];
__device__ float g_s2[B_SZ * CIN];
__device__ float g_d1[B_SZ * N1];
__device__ float g_d2[B_SZ * N2];
__device__ __half g_xp [NPIX * CIN];     // conv1 input, modulated by s1
__device__ __half g_x2p[NPIX * CIN];     // conv2 input (h * s2)
__device__ __half g_w1h[9 * N1 * CIN];   // [tap][n][ci]
__device__ __half g_w1l[9 * N1 * CIN];
__device__ __half g_w2h[9 * N2 * CIN];
__device__ __half g_w2l[9 * N2 * CIN];

// ---------------------------------------------------------------------------
// low-level helpers
// ---------------------------------------------------------------------------
__device__ __forceinline__ uint32_t smem_to_u32(const void* p) {
    uint32_t a;
    asm("{ .reg .u64 t; cvta.to.shared.u64 t, %1; cvt.u32.u64 %0, t; }" : "=r"(a) : "l"(p));
    return a;
}

#define MBARRIER_INIT(addr, count) \
    asm volatile("mbarrier.init.shared.b64 [%0], %1;" :: "r"((uint32_t)(addr)), "r"((uint32_t)(count)) : "memory")

#define MBARRIER_EXPECT_TX(addr, tx) \
    asm volatile("mbarrier.arrive.expect_tx.shared.b64 _, [%0], %1;" :: "r"((uint32_t)(addr)), "r"((uint32_t)(tx)) : "memory")

#define MBARRIER_WAIT_PARITY(mbar_smem_addr, phase_parity) do { \
    uint32_t _mbar = (uint32_t)(mbar_smem_addr); \
    uint32_t _parity = (uint32_t)(phase_parity); \
    uint32_t _done; \
    asm volatile( \
        "{\n\t.reg .pred p;\n\t" \
        "mbarrier.try_wait.parity.acquire.cta.shared::cta.b64 p, [%1], %2;\n\t" \
        "selp.b32 %0, 1, 0, p;\n\t}" \
        : "=r"(_done) : "r"(_mbar), "r"(_parity) : "memory"); \
    if (!_done) { \
        asm volatile( \
            "{\n\t.reg .pred P1;\n\t" \
            "WAIT_LOOP_%=:\n\t" \
            "mbarrier.try_wait.parity.acquire.cta.shared::cta.b64 P1, [%0], %1, 0x989680;\n\t" \
            "@P1 bra.uni WAIT_DONE_%=;\n\t" \
            "bra.uni WAIT_LOOP_%=;\n\t" \
            "WAIT_DONE_%=:\n\t}" \
            :: "r"(_mbar), "r"(_parity) : "memory"); \
    } \
} while(0)

#define TMA_LOAD_2D(smem_addr, tensor_map, cx, cy, mbar) \
    asm volatile( \
        "cp.async.bulk.tensor.2d.shared::cta.global.tile.mbarrier::complete_tx::bytes " \
        "[%0], [%1, {%2, %3}], [%4];" \
        :: "r"((uint32_t)(smem_addr)), "l"(tensor_map), \
           "r"((int32_t)(cx)), "r"((int32_t)(cy)), "r"((uint32_t)(mbar)) : "memory")

#define TMA_LOAD_3D(smem_addr, tensor_map, cx, cy, cz, mbar) \
    asm volatile( \
        "cp.async.bulk.tensor.3d.shared::cta.global.tile.mbarrier::complete_tx::bytes " \
        "[%0], [%1, {%2, %3, %4}], [%5];" \
        :: "r"((uint32_t)(smem_addr)), "l"(tensor_map), \
           "r"((int32_t)(cx)), "r"((int32_t)(cy)), "r"((int32_t)(cz)), \
           "r"((uint32_t)(mbar)) : "memory")

#define LDSM4(r, addr) \
    asm volatile("ldmatrix.sync.aligned.m8n8.x4.shared.b16 {%0,%1,%2,%3}, [%4];" \
        : "=r"((r)[0]), "=r"((r)[1]), "=r"((r)[2]), "=r"((r)[3]) : "r"(addr))

#define MMA16816(d, a, b0_, b1_) \
    asm volatile("mma.sync.aligned.m16n8k16.row.col.f32.f16.f16.f32 " \
        "{%0,%1,%2,%3}, {%4,%5,%6,%7}, {%8,%9}, {%0,%1,%2,%3};" \
        : "+f"((d)[0]), "+f"((d)[1]), "+f"((d)[2]), "+f"((d)[3]) \
        : "r"((a)[0]), "r"((a)[1]), "r"((a)[2]), "r"((a)[3]), "r"(b0_), "r"(b1_))

// ---------------------------------------------------------------------------
// prep 1: styles
// ---------------------------------------------------------------------------
__global__ void style_all(const float* __restrict__ w,
                          const float* __restrict__ a1w, const float* __restrict__ a1b,
                          const float* __restrict__ a2w, const float* __restrict__ a2b)
{
    int b = blockIdx.x, ci = threadIdx.x, which = blockIdx.y;
    const float* aw = which ? a2w : a1w;
    const float* ab = which ? a2b : a1b;
    float sum = ab[ci];
    const float* wr = w + b * WDIM;
    #pragma unroll 8
    for (int k = 0; k < WDIM; ++k) sum += wr[k] * aw[k * CIN + ci];
    (which ? g_s2 : g_s1)[b * CIN + ci] = sum;
}

// ---------------------------------------------------------------------------
// prep 2: demod (ksq fused)
// ---------------------------------------------------------------------------
__global__ void demod_all(const float* __restrict__ k1, const float* __restrict__ k2)
{
    const int blkx = blockIdx.x;
    const int conv = (blkx >= 2);
    const int NT   = conv ? N2 : N1;
    const int co   = (conv ? (blkx - 2) : blkx) * 128 + threadIdx.x;
    const int b    = blockIdx.y;
    const float* kern = conv ? k2 : k1;
    const float* st   = conv ? g_s2 : g_s1;

    __shared__ float ssq[CIN];
    for (int i = threadIdx.x; i < CIN; i += 128) {
        float s = st[b * CIN + i];
        ssq[i] = s * s;
    }
    __syncthreads();

    float acc = 0.f;
    for (int ci = 0; ci < CIN; ++ci) {
        float kv = 0.f;
        #pragma unroll
        for (int p = 0; p < 9; ++p) {
            float v = kern[((size_t)p * CIN + ci) * NT + co];
            kv += v * v;
        }
        acc += ssq[ci] * kv;
    }
    (conv ? g_d2 : g_d1)[b * NT + co] = rsqrtf(acc + 1e-8f);
}

// ---------------------------------------------------------------------------
// prep 3: weight transpose + fp16 hi/lo split, ci-fastest (coalesced stores)
// ---------------------------------------------------------------------------
__global__ void wsplit_all(const float* __restrict__ k1, const float* __restrict__ k2)
{
    const int conv = blockIdx.y;
    const int NT   = conv ? N2 : N1;
    const int idx  = blockIdx.x * blockDim.x + threadIdx.x;   // over 9*NT*128
    if (idx >= 9 * NT * 128) return;
    const int g   = idx & 127;              // ci pair index
    const int n   = (idx >> 7) % NT;
    const int tap = (idx >> 7) / NT;
    const int ci  = g * 2;
    const float* kern = conv ? k2 : k1;
    const float v0 = kern[((size_t)(tap * CIN + ci))     * NT + n];
    const float v1 = kern[((size_t)(tap * CIN + ci + 1)) * NT + n];
    const __half h0 = __float2half_rn(v0);
    const __half h1 = __float2half_rn(v1);
    const __half l0 = __float2half_rn(v0 - __half2float(h0));
    const __half l1 = __float2half_rn(v1 - __half2float(h1));
    const size_t o = ((size_t)tap * NT + n) * CIN + ci;
    if (conv == 0) {
        *reinterpret_cast<__half2*>(g_w1h + o) = __halves2half2(h0, h1);
        *reinterpret_cast<__half2*>(g_w1l + o) = __halves2half2(l0, l1);
    } else {
        *reinterpret_cast<__half2*>(g_w2h + o) = __halves2half2(h0, h1);
        *reinterpret_cast<__half2*>(g_w2l + o) = __halves2half2(l0, l1);
    }
}

// ---------------------------------------------------------------------------
// prep 4: pad + modulate-by-s1 -> single fp16 plane; zero x2p borders.
// ---------------------------------------------------------------------------
__global__ void pad_kernel(const float* __restrict__ x)
{
    const int tid = threadIdx.x;
    const int pix = blockIdx.x * 4 + (tid >> 6);     // 0 .. NPIX-1
    const int ci  = (tid & 63) << 2;
    const int b  = pix / (PW * PW);
    const int r  = pix % (PW * PW);
    const int hp = r / PW, wp = r % PW;
    const bool interior = (hp >= 1) && (hp <= H_SZ) && (wp >= 1) && (wp <= W_SZ);

    uint2 packed = make_uint2(0u, 0u);
    if (interior) {
        const float4 v = *reinterpret_cast<const float4*>(
            x + (((size_t)b * H_SZ + (hp - 1)) * W_SZ + (wp - 1)) * CIN + ci);
        const float4 s = *reinterpret_cast<const float4*>(g_s1 + b * CIN + ci);
        __half2 p0 = __halves2half2(__float2half_rn(v.x * s.x), __float2half_rn(v.y * s.y));
        __half2 p1 = __halves2half2(__float2half_rn(v.z * s.z), __float2half_rn(v.w * s.w));
        packed.x = *reinterpret_cast<uint32_t*>(&p0);
        packed.y = *reinterpret_cast<uint32_t*>(&p1);
    }
    const size_t o = (size_t)pix * CIN + ci;
    *reinterpret_cast<uint2*>(g_xp + o) = packed;
    if (!interior)
        *reinterpret_cast<uint2*>(g_x2p + o) = make_uint2(0u, 0u);
}

// ---------------------------------------------------------------------------
// conv GEMM. CTA: 128 pixels (2 image rows) x 128 output channels.
// 256 threads, 8 warps (4m x 2n), warp tile 32x64, 2 CTAs/SM.
// Producer: single thread, TMA bulk-tensor loads into 80B-pitch rows
// (box width 40 halves; cols 32..39 zero-filled / unused pad).
//   A: slab of 264 pixel rows per ci-chunk, loaded as 2 boxes of 136 rows
//      (second box at +10880 = 85*128, keeping 128B TMA alignment; the 8
//      extra rows per box are zero-filled overlap-slack, never consumed).
//   W: 128co x 32ci hi+lo per tap-stage (2 TMA), dbl-buffered.
// MMA passes per tap: A*Wh + A*Wl.
// ---------------------------------------------------------------------------
#define ROWB       80
#define A_BOX_H    136
#define A_BOX_B    (A_BOX_H * ROWB)       // 10880 = 85*128
#define A_PLANE_B  (2 * A_BOX_B)          // 21760
#define W_PLANE_B  (128 * ROWB)           // 10240
#define W_BUF_B    (2 * W_PLANE_B)        // 20480 (hi+lo)
#define SM_CTRL    1024                   // mbarriers live here
#define SMEM_TOTAL (SM_CTRL + 2 * A_PLANE_B + 2 * W_BUF_B)   // 85504

template<int CONV>
__global__ void __launch_bounds__(256, 2)
conv_mma(const __grid_constant__ CUtensorMap mA,
         const __grid_constant__ CUtensorMap mWh,
         const __grid_constant__ CUtensorMap mWl,
         const float* __restrict__ noise,
         const float* __restrict__ nscale,
         const float* __restrict__ bias,
         float* __restrict__ outp)
{
    constexpr int NTOT = CONV ? N2 : N1;
    extern __shared__ __align__(128) char smem[];
    const uint32_t sb  = smem_to_u32(smem);       // mbarriers: A @ +0,+8; W @ +16,+24
    const uint32_t sbD = sb + SM_CTRL;
    const uint32_t sbW = sbD + 2 * A_PLANE_B;

    const int tid  = threadIdx.x;
    const int lane = tid & 31;
    const int warp = tid >> 5;
    const int wm   = warp >> 1;          // 0..3  (32-row m slice)
    const int wn   = warp & 1;           // 0..1  (64-col n slice)

    const int mtile = blockIdx.y;        // 0..511
    const int b  = mtile >> 5;
    const int R  = (mtile & 31) << 1;    // first output image row
    const int n0 = blockIdx.x << 7;
    const int pixBase = (b * PW + R) * PW;

    if (tid == 0) {
        MBARRIER_INIT(sb + 0, 1);  MBARRIER_INIT(sb + 8, 1);
        MBARRIER_INIT(sb + 16, 1); MBARRIER_INIT(sb + 24, 1);
    }
    __syncthreads();

    // ---- ldmatrix fragment smem offsets (relative to buffer base) ----
    uint32_t a_base[2];
    #pragma unroll
    for (int mf = 0; mf < 2; ++mf) {
        const int m    = wm * 32 + mf * 16 + (lane & 15);
        const int srow = (m >> 6) * 66 + (m & 63);      // slab pixel-row (tap 0)
        a_base[mf] = (uint32_t)(srow * ROWB + ((lane >> 4) << 4));
    }
    uint32_t b_off[4];
    #pragma unroll
    for (int nf = 0; nf < 4; ++nf)
        b_off[nf] = (uint32_t)((wn * 64 + nf * 16 + (lane & 7) + ((lane >> 4) << 3)) * ROWB
                               + (((lane >> 3) & 1) << 4));

    float acc[2][8][4];
    #pragma unroll
    for (int i = 0; i < 2; ++i)
        #pragma unroll
        for (int j = 0; j < 8; ++j)
            #pragma unroll
            for (int k = 0; k < 4; ++k) acc[i][j][k] = 0.f;

    // ---- prologue: A chunk 0 + W stage 0 ----
    if (tid == 0) {
        MBARRIER_EXPECT_TX(sb + 0, A_PLANE_B);                  // 21760
        TMA_LOAD_2D(sbD,           &mA, 0, pixBase,           sb + 0);
        TMA_LOAD_2D(sbD + A_BOX_B, &mA, 0, pixBase + A_BOX_H, sb + 0);
        MBARRIER_EXPECT_TX(sb + 16, W_BUF_B);                   // 20480
        TMA_LOAD_3D(sbW,             &mWh, 0, n0, 0, sb + 16);
        TMA_LOAD_3D(sbW + W_PLANE_B, &mWl, 0, n0, 0, sb + 16);
    }

    uint32_t phA0 = 0, phA1 = 0, phW0 = 0, phW1 = 0;

    // ---- main loop: 8 chunks x 9 taps ----
    int s = 0;
    #pragma unroll 1
    for (int c = 0; c < 8; ++c) {
        const uint32_t Ab = sbD + (c & 1) * A_PLANE_B;
        #pragma unroll 1
        for (int t = 0; t < 9; ++t, ++s) {
            if (tid == 0 && s + 1 < 72) {
                const int nc = (t == 8) ? c + 1 : c;
                const int nt = (t == 8) ? 0 : t + 1;
                const uint32_t wb = sbW + ((s + 1) & 1) * W_BUF_B;
                const uint32_t mb = sb + 16 + ((s + 1) & 1) * 8;
                MBARRIER_EXPECT_TX(mb, W_BUF_B);
                TMA_LOAD_3D(wb,             &mWh, nc * 32, n0, nt, mb);
                TMA_LOAD_3D(wb + W_PLANE_B, &mWl, nc * 32, n0, nt, mb);
            }
            if (t == 0) {
                if (tid == 0 && c < 7) {
                    const uint32_t ab2 = sbD + ((c + 1) & 1) * A_PLANE_B;
                    const uint32_t mb  = sb + ((c + 1) & 1) * 8;
                    MBARRIER_EXPECT_TX(mb, A_PLANE_B);          // 21760
                    TMA_LOAD_2D(ab2,           &mA, (c + 1) * 32, pixBase,           mb);
                    TMA_LOAD_2D(ab2 + A_BOX_B, &mA, (c + 1) * 32, pixBase + A_BOX_H, mb);
                }
                if (c & 1) { MBARRIER_WAIT_PARITY(sb + 8, phA1); phA1 ^= 1; }
                else       { MBARRIER_WAIT_PARITY(sb + 0, phA0); phA0 ^= 1; }
            }
            if (s & 1) { MBARRIER_WAIT_PARITY(sb + 24, phW1); phW1 ^= 1; }
            else       { MBARRIER_WAIT_PARITY(sb + 16, phW0); phW0 ^= 1; }

            // ---- compute tap t on chunk c ----
            const uint32_t Wb   = sbW + (s & 1) * W_BUF_B;
            const uint32_t Aofs = (uint32_t)(((t / 3) * 66 + (t % 3)) * ROWB);
            #pragma unroll
            for (int ks = 0; ks < 2; ++ks) {
                uint32_t a0[4], a1r[4];
                LDSM4(a0,  Ab + Aofs + a_base[0] + ks * 32);
                LDSM4(a1r, Ab + Aofs + a_base[1] + ks * 32);
                #pragma unroll
                for (int nf = 0; nf < 4; ++nf) {
                    uint32_t bh[4], bl[4];
                    LDSM4(bh, Wb + b_off[nf] + ks * 32);
                    MMA16816(acc[0][nf * 2],     a0,  bh[0], bh[1]);
                    MMA16816(acc[0][nf * 2 + 1], a0,  bh[2], bh[3]);
                    MMA16816(acc[1][nf * 2],     a1r, bh[0], bh[1]);
                    MMA16816(acc[1][nf * 2 + 1], a1r, bh[2], bh[3]);
                    LDSM4(bl, Wb + W_PLANE_B + b_off[nf] + ks * 32);
                    MMA16816(acc[0][nf * 2],     a0,  bl[0], bl[1]);
                    MMA16816(acc[0][nf * 2 + 1], a0,  bl[2], bl[3]);
                    MMA16816(acc[1][nf * 2],     a1r, bl[0], bl[1]);
                    MMA16816(acc[1][nf * 2 + 1], a1r, bl[2], bl[3]);
                }
            }
            __syncthreads();
        }
    }

    // ---- epilogue ----
    const float ns = nscale[0];
    const float* __restrict__ dm = (CONV ? g_d2 : g_d1) + b * NTOT;
    const int q2 = (lane & 3) * 2;
    const int rr = lane >> 2;

    #pragma unroll
    for (int mf = 0; mf < 2; ++mf) {
        #pragma unroll
        for (int hf = 0; hf < 2; ++hf) {
            const int ml = wm * 32 + mf * 16 + rr + hf * 8;    // 0..127
            const int h  = R + (ml >> 6);
            const int w  = ml & 63;
            const float nz = noise[((size_t)b * H_SZ + h) * W_SZ + w] * ns;
            #pragma unroll
            for (int nf = 0; nf < 8; ++nf) {
                const int co = n0 + wn * 64 + nf * 8 + q2;
                float v0 = acc[mf][nf][hf * 2]     * dm[co]     + nz + bias[co];
                float v1 = acc[mf][nf][hf * 2 + 1] * dm[co + 1] + nz + bias[co + 1];
                v0 = (v0 > 0.f) ? v0 : 0.2f * v0;
                v1 = (v1 > 0.f) ? v1 : 0.2f * v1;
                if (CONV == 0) {
                    const float m0 = v0 * g_s2[b * CIN + co];
                    const float m1 = v1 * g_s2[b * CIN + co + 1];
                    const size_t o = ((size_t)(b * PW + h + 1) * PW + (w + 1)) * CIN + co;
                    *reinterpret_cast<__half2*>(g_x2p + o) =
                        __halves2half2(__float2half_rn(m0), __float2half_rn(m1));
                } else {
                    const int sh = co >> 8, sw = (co >> 7) & 1, c2 = co & 127;
                    float2 vv = make_float2(v0, v1);
                    *reinterpret_cast<float2*>(
                        outp + (((size_t)(b * 128 + 2 * h + sh)) * 128 + (2 * w + sw)) * 128 + c2) = vv;
                }
            }
        }
    }
}

// ---------------------------------------------------------------------------
// host
// ---------------------------------------------------------------------------
typedef CUresult (*PFN_tmap)(CUtensorMap*, CUtensorMapDataType, cuuint32_t, void*,
                             const cuuint64_t*, const cuuint64_t*, const cuuint32_t*,
                             const cuuint32_t*, CUtensorMapInterleave, CUtensorMapSwizzle,
                             CUtensorMapL2promotion, CUtensorMapFloatOOBfill);

static void encA(PFN_tmap fn, CUtensorMap* m, void* ptr)
{
    cuuint64_t dims[2]    = {CIN, NPIX};
    cuuint64_t strides[1] = {CIN * 2};
    cuuint32_t box[2]     = {40, A_BOX_H};
    cuuint32_t es[2]      = {1, 1};
    fn(m, CU_TENSOR_MAP_DATA_TYPE_FLOAT16, 2, ptr, dims, strides, box, es,
       CU_TENSOR_MAP_INTERLEAVE_NONE, CU_TENSOR_MAP_SWIZZLE_NONE,
       CU_TENSOR_MAP_L2_PROMOTION_L2_128B, CU_TENSOR_MAP_FLOAT_OOB_FILL_NONE);
}

static void encW(PFN_tmap fn, CUtensorMap* m, void* ptr, uint64_t ntot)
{
    cuuint64_t dims[3]    = {CIN, ntot, 9};
    cuuint64_t strides[2] = {CIN * 2, ntot * CIN * 2};
    cuuint32_t box[3]     = {40, 128, 1};
    cuuint32_t es[3]      = {1, 1, 1};
    fn(m, CU_TENSOR_MAP_DATA_TYPE_FLOAT16, 3, ptr, dims, strides, box, es,
       CU_TENSOR_MAP_INTERLEAVE_NONE, CU_TENSOR_MAP_SWIZZLE_NONE,
       CU_TENSOR_MAP_L2_PROMOTION_L2_128B, CU_TENSOR_MAP_FLOAT_OOB_FILL_NONE);
}

extern "C" void kernel_launch(void* const* d_in, const int* in_sizes, int n_in,
                              void* d_out, int out_size)
{
    const float* x    = (const float*)d_in[0];
    const float* w    = (const float*)d_in[1];
    const float* a1w  = (const float*)d_in[2];
    const float* a1b  = (const float*)d_in[3];
    const float* k1   = (const float*)d_in[4];
    const float* ns1  = (const float*)d_in[5];
    const float* b1   = (const float*)d_in[6];
    const float* a2w  = (const float*)d_in[7];
    const float* a2b  = (const float*)d_in[8];
    const float* k2   = (const float*)d_in[9];
    const float* ns2  = (const float*)d_in[10];
    const float* b2   = (const float*)d_in[11];
    const float* noi1 = (const float*)d_in[12];
    const float* noi2 = (const float*)d_in[13];
    float* outp = (float*)d_out;

    void* sym = nullptr;
    cudaDriverEntryPointQueryResult qres;
    cudaGetDriverEntryPoint("cuTensorMapEncodeTiled", &sym, cudaEnableDefault, &qres);
    PFN_tmap enc = (PFN_tmap)sym;

    void *pxp, *px2p, *pw1h, *pw1l, *pw2h, *pw2l;
    cudaGetSymbolAddress(&pxp,  g_xp);   cudaGetSymbolAddress(&px2p, g_x2p);
    cudaGetSymbolAddress(&pw1h, g_w1h);  cudaGetSymbolAddress(&pw1l, g_w1l);
    cudaGetSymbolAddress(&pw2h, g_w2h);  cudaGetSymbolAddress(&pw2l, g_w2l);

    CUtensorMap mA1, mA2, mW1h, mW1l, mW2h, mW2l;
    encA(enc, &mA1, pxp);
    encA(enc, &mA2, px2p);
    encW(enc, &mW1h, pw1h, N1);
    encW(enc, &mW1l, pw1l, N1);
    encW(enc, &mW2h, pw2h, N2);
    encW(enc, &mW2l, pw2l, N2);

    cudaFuncSetAttribute(conv_mma<0>, cudaFuncAttributeMaxDynamicSharedMemorySize, SMEM_TOTAL);
    cudaFuncSetAttribute(conv_mma<1>, cudaFuncAttributeMaxDynamicSharedMemorySize, SMEM_TOTAL);

    // prep
    { dim3 g(B_SZ, 2);  style_all<<<g, CIN>>>(w, a1w, a1b, a2w, a2b); }
    { dim3 g(6, B_SZ);  demod_all<<<g, 128>>>(k1, k2); }
    { dim3 g((9 * N2 * 128 + 255) / 256, 2); wsplit_all<<<g, 256>>>(k1, k2); }
    pad_kernel<<<NPIX / 4, 256>>>(x);

    // conv1: xp -> x2p (epilogue multiplies by s2, single fp16 plane)
    {
        dim3 grid(N1 / 128, 512);
        conv_mma<0><<<grid, 256, SMEM_TOTAL>>>(mA1, mW1h, mW1l, noi1, ns1, b1, nullptr);
    }
    // conv2: x2p -> d_out (pixel shuffled)
    {
        dim3 grid(N2 / 128, 512);
        conv_mma<1><<<grid, 256, SMEM_TOTAL>>>(mA2, mW2h, mW2l, noi2, ns2, b2, outp);
    }
}

// round 8
// speedup vs baseline: 11.5461x; 1.6129x over previous
#include <cuda_runtime.h>
#include <cuda.h>
#include <cuda_fp16.h>
#include <cstdint>

// ---------------------------------------------------------------------------
// SynthesisBlock via mma.sync (HMMA), TMA bulk-tensor producers.
// R8 = R7 with single-plane fp16 W (1 MMA pass instead of 2).
// Error model: A-quant (2.8e-4 RMS) + W-quant (2.8e-4) in quadrature ~ 4.1e-4.
// ---------------------------------------------------------------------------
#define B_SZ 16
#define H_SZ 64
#define W_SZ 64
#define CIN  256
#define N1   256
#define N2   512
#define WDIM 128
#define PW   66          // padded H/W
#define NPIX (B_SZ * PW * PW)

// ---- device scratch ----
__device__ float g_s1[B_SZ * CIN];
__device__ float g_s2[B_SZ * CIN];
__device__ float g_d1[B_SZ * N1];
__device__ float g_d2[B_SZ * N2];
__device__ __half g_xp [NPIX * CIN];     // conv1 input, modulated by s1
__device__ __half g_x2p[NPIX * CIN];     // conv2 input (h * s2)
__device__ __half g_w1h[9 * N1 * CIN];   // [tap][n][ci]
__device__ __half g_w2h[9 * N2 * CIN];

// ---------------------------------------------------------------------------
// low-level helpers
// ---------------------------------------------------------------------------
__device__ __forceinline__ uint32_t smem_to_u32(const void* p) {
    uint32_t a;
    asm("{ .reg .u64 t; cvta.to.shared.u64 t, %1; cvt.u32.u64 %0, t; }" : "=r"(a) : "l"(p));
    return a;
}

#define MBARRIER_INIT(addr, count) \
    asm volatile("mbarrier.init.shared.b64 [%0], %1;" :: "r"((uint32_t)(addr)), "r"((uint32_t)(count)) : "memory")

#define MBARRIER_EXPECT_TX(addr, tx) \
    asm volatile("mbarrier.arrive.expect_tx.shared.b64 _, [%0], %1;" :: "r"((uint32_t)(addr)), "r"((uint32_t)(tx)) : "memory")

#define MBARRIER_WAIT_PARITY(mbar_smem_addr, phase_parity) do { \
    uint32_t _mbar = (uint32_t)(mbar_smem_addr); \
    uint32_t _parity = (uint32_t)(phase_parity); \
    uint32_t _done; \
    asm volatile( \
        "{\n\t.reg .pred p;\n\t" \
        "mbarrier.try_wait.parity.acquire.cta.shared::cta.b64 p, [%1], %2;\n\t" \
        "selp.b32 %0, 1, 0, p;\n\t}" \
        : "=r"(_done) : "r"(_mbar), "r"(_parity) : "memory"); \
    if (!_done) { \
        asm volatile( \
            "{\n\t.reg .pred P1;\n\t" \
            "WAIT_LOOP_%=:\n\t" \
            "mbarrier.try_wait.parity.acquire.cta.shared::cta.b64 P1, [%0], %1, 0x989680;\n\t" \
            "@P1 bra.uni WAIT_DONE_%=;\n\t" \
            "bra.uni WAIT_LOOP_%=;\n\t" \
            "WAIT_DONE_%=:\n\t}" \
            :: "r"(_mbar), "r"(_parity) : "memory"); \
    } \
} while(0)

#define TMA_LOAD_2D(smem_addr, tensor_map, cx, cy, mbar) \
    asm volatile( \
        "cp.async.bulk.tensor.2d.shared::cta.global.tile.mbarrier::complete_tx::bytes " \
        "[%0], [%1, {%2, %3}], [%4];" \
        :: "r"((uint32_t)(smem_addr)), "l"(tensor_map), \
           "r"((int32_t)(cx)), "r"((int32_t)(cy)), "r"((uint32_t)(mbar)) : "memory")

#define TMA_LOAD_3D(smem_addr, tensor_map, cx, cy, cz, mbar) \
    asm volatile( \
        "cp.async.bulk.tensor.3d.shared::cta.global.tile.mbarrier::complete_tx::bytes " \
        "[%0], [%1, {%2, %3, %4}], [%5];" \
        :: "r"((uint32_t)(smem_addr)), "l"(tensor_map), \
           "r"((int32_t)(cx)), "r"((int32_t)(cy)), "r"((int32_t)(cz)), \
           "r"((uint32_t)(mbar)) : "memory")

#define LDSM4(r, addr) \
    asm volatile("ldmatrix.sync.aligned.m8n8.x4.shared.b16 {%0,%1,%2,%3}, [%4];" \
        : "=r"((r)[0]), "=r"((r)[1]), "=r"((r)[2]), "=r"((r)[3]) : "r"(addr))

#define MMA16816(d, a, b0_, b1_) \
    asm volatile("mma.sync.aligned.m16n8k16.row.col.f32.f16.f16.f32 " \
        "{%0,%1,%2,%3}, {%4,%5,%6,%7}, {%8,%9}, {%0,%1,%2,%3};" \
        : "+f"((d)[0]), "+f"((d)[1]), "+f"((d)[2]), "+f"((d)[3]) \
        : "r"((a)[0]), "r"((a)[1]), "r"((a)[2]), "r"((a)[3]), "r"(b0_), "r"(b1_))

// ---------------------------------------------------------------------------
// prep 1: styles
// ---------------------------------------------------------------------------
__global__ void style_all(const float* __restrict__ w,
                          const float* __restrict__ a1w, const float* __restrict__ a1b,
                          const float* __restrict__ a2w, const float* __restrict__ a2b)
{
    int b = blockIdx.x, ci = threadIdx.x, which = blockIdx.y;
    const float* aw = which ? a2w : a1w;
    const float* ab = which ? a2b : a1b;
    float sum = ab[ci];
    const float* wr = w + b * WDIM;
    #pragma unroll 8
    for (int k = 0; k < WDIM; ++k) sum += wr[k] * aw[k * CIN + ci];
    (which ? g_s2 : g_s1)[b * CIN + ci] = sum;
}

// ---------------------------------------------------------------------------
// prep 2: demod (ksq fused)
// ---------------------------------------------------------------------------
__global__ void demod_all(const float* __restrict__ k1, const float* __restrict__ k2)
{
    const int blkx = blockIdx.x;
    const int conv = (blkx >= 2);
    const int NT   = conv ? N2 : N1;
    const int co   = (conv ? (blkx - 2) : blkx) * 128 + threadIdx.x;
    const int b    = blockIdx.y;
    const float* kern = conv ? k2 : k1;
    const float* st   = conv ? g_s2 : g_s1;

    __shared__ float ssq[CIN];
    for (int i = threadIdx.x; i < CIN; i += 128) {
        float s = st[b * CIN + i];
        ssq[i] = s * s;
    }
    __syncthreads();

    float acc = 0.f;
    for (int ci = 0; ci < CIN; ++ci) {
        float kv = 0.f;
        #pragma unroll
        for (int p = 0; p < 9; ++p) {
            float v = kern[((size_t)p * CIN + ci) * NT + co];
            kv += v * v;
        }
        acc += ssq[ci] * kv;
    }
    (conv ? g_d2 : g_d1)[b * NT + co] = rsqrtf(acc + 1e-8f);
}

// ---------------------------------------------------------------------------
// prep 3: weight transpose + fp16 round, ci-fastest (coalesced stores)
// ---------------------------------------------------------------------------
__global__ void wsplit_all(const float* __restrict__ k1, const float* __restrict__ k2)
{
    const int conv = blockIdx.y;
    const int NT   = conv ? N2 : N1;
    const int idx  = blockIdx.x * blockDim.x + threadIdx.x;   // over 9*NT*128
    if (idx >= 9 * NT * 128) return;
    const int g   = idx & 127;              // ci pair index
    const int n   = (idx >> 7) % NT;
    const int tap = (idx >> 7) / NT;
    const int ci  = g * 2;
    const float* kern = conv ? k2 : k1;
    const float v0 = kern[((size_t)(tap * CIN + ci))     * NT + n];
    const float v1 = kern[((size_t)(tap * CIN + ci + 1)) * NT + n];
    const size_t o = ((size_t)tap * NT + n) * CIN + ci;
    const __half2 hv = __halves2half2(__float2half_rn(v0), __float2half_rn(v1));
    if (conv == 0) *reinterpret_cast<__half2*>(g_w1h + o) = hv;
    else           *reinterpret_cast<__half2*>(g_w2h + o) = hv;
}

// ---------------------------------------------------------------------------
// prep 4: pad + modulate-by-s1 -> single fp16 plane; zero x2p borders.
// ---------------------------------------------------------------------------
__global__ void pad_kernel(const float* __restrict__ x)
{
    const int tid = threadIdx.x;
    const int pix = blockIdx.x * 4 + (tid >> 6);     // 0 .. NPIX-1
    const int ci  = (tid & 63) << 2;
    const int b  = pix / (PW * PW);
    const int r  = pix % (PW * PW);
    const int hp = r / PW, wp = r % PW;
    const bool interior = (hp >= 1) && (hp <= H_SZ) && (wp >= 1) && (wp <= W_SZ);

    uint2 packed = make_uint2(0u, 0u);
    if (interior) {
        const float4 v = *reinterpret_cast<const float4*>(
            x + (((size_t)b * H_SZ + (hp - 1)) * W_SZ + (wp - 1)) * CIN + ci);
        const float4 s = *reinterpret_cast<const float4*>(g_s1 + b * CIN + ci);
        __half2 p0 = __halves2half2(__float2half_rn(v.x * s.x), __float2half_rn(v.y * s.y));
        __half2 p1 = __halves2half2(__float2half_rn(v.z * s.z), __float2half_rn(v.w * s.w));
        packed.x = *reinterpret_cast<uint32_t*>(&p0);
        packed.y = *reinterpret_cast<uint32_t*>(&p1);
    }
    const size_t o = (size_t)pix * CIN + ci;
    *reinterpret_cast<uint2*>(g_xp + o) = packed;
    if (!interior)
        *reinterpret_cast<uint2*>(g_x2p + o) = make_uint2(0u, 0u);
}

// ---------------------------------------------------------------------------
// conv GEMM. CTA: 128 pixels (2 image rows) x 128 output channels.
// 256 threads, 8 warps (4m x 2n), warp tile 32x64, 2 CTAs/SM.
// Producer: single thread, TMA bulk-tensor loads into 80B-pitch rows.
//   A: slab of 264 pixel rows per ci-chunk (2 boxes of 136 rows, 128B-aligned
//      destinations), double-buffered, reused by all 9 taps via row offset.
//   W: 128co x 32ci single fp16 plane per tap-stage (1 TMA), dbl-buffered.
// MMA: single pass A*W per tap.
// ---------------------------------------------------------------------------
#define ROWB       80
#define A_BOX_H    136
#define A_BOX_B    (A_BOX_H * ROWB)       // 10880 = 85*128
#define A_PLANE_B  (2 * A_BOX_B)          // 21760
#define W_PLANE_B  (128 * ROWB)           // 10240
#define SM_CTRL    1024                   // mbarriers live here
#define SMEM_TOTAL (SM_CTRL + 2 * A_PLANE_B + 2 * W_PLANE_B)   // 65024

template<int CONV>
__global__ void __launch_bounds__(256, 2)
conv_mma(const __grid_constant__ CUtensorMap mA,
         const __grid_constant__ CUtensorMap mWh,
         const float* __restrict__ noise,
         const float* __restrict__ nscale,
         const float* __restrict__ bias,
         float* __restrict__ outp)
{
    constexpr int NTOT = CONV ? N2 : N1;
    extern __shared__ __align__(128) char smem[];
    const uint32_t sb  = smem_to_u32(smem);       // mbarriers: A @ +0,+8; W @ +16,+24
    const uint32_t sbD = sb + SM_CTRL;
    const uint32_t sbW = sbD + 2 * A_PLANE_B;

    const int tid  = threadIdx.x;
    const int lane = tid & 31;
    const int warp = tid >> 5;
    const int wm   = warp >> 1;          // 0..3  (32-row m slice)
    const int wn   = warp & 1;           // 0..1  (64-col n slice)

    const int mtile = blockIdx.y;        // 0..511
    const int b  = mtile >> 5;
    const int R  = (mtile & 31) << 1;    // first output image row
    const int n0 = blockIdx.x << 7;
    const int pixBase = (b * PW + R) * PW;

    if (tid == 0) {
        MBARRIER_INIT(sb + 0, 1);  MBARRIER_INIT(sb + 8, 1);
        MBARRIER_INIT(sb + 16, 1); MBARRIER_INIT(sb + 24, 1);
    }
    __syncthreads();

    // ---- ldmatrix fragment smem offsets (relative to buffer base) ----
    uint32_t a_base[2];
    #pragma unroll
    for (int mf = 0; mf < 2; ++mf) {
        const int m    = wm * 32 + mf * 16 + (lane & 15);
        const int srow = (m >> 6) * 66 + (m & 63);      // slab pixel-row (tap 0)
        a_base[mf] = (uint32_t)(srow * ROWB + ((lane >> 4) << 4));
    }
    uint32_t b_off[4];
    #pragma unroll
    for (int nf = 0; nf < 4; ++nf)
        b_off[nf] = (uint32_t)((wn * 64 + nf * 16 + (lane & 7) + ((lane >> 4) << 3)) * ROWB
                               + (((lane >> 3) & 1) << 4));

    float acc[2][8][4];
    #pragma unroll
    for (int i = 0; i < 2; ++i)
        #pragma unroll
        for (int j = 0; j < 8; ++j)
            #pragma unroll
            for (int k = 0; k < 4; ++k) acc[i][j][k] = 0.f;

    // ---- prologue: A chunk 0 + W stage 0 ----
    if (tid == 0) {
        MBARRIER_EXPECT_TX(sb + 0, A_PLANE_B);                  // 21760
        TMA_LOAD_2D(sbD,           &mA, 0, pixBase,           sb + 0);
        TMA_LOAD_2D(sbD + A_BOX_B, &mA, 0, pixBase + A_BOX_H, sb + 0);
        MBARRIER_EXPECT_TX(sb + 16, W_PLANE_B);                 // 10240
        TMA_LOAD_3D(sbW, &mWh, 0, n0, 0, sb + 16);
    }

    uint32_t phA0 = 0, phA1 = 0, phW0 = 0, phW1 = 0;

    // ---- main loop: 8 chunks x 9 taps ----
    int s = 0;
    #pragma unroll 1
    for (int c = 0; c < 8; ++c) {
        const uint32_t Ab = sbD + (c & 1) * A_PLANE_B;
        #pragma unroll 1
        for (int t = 0; t < 9; ++t, ++s) {
            if (tid == 0 && s + 1 < 72) {
                const int nc = (t == 8) ? c + 1 : c;
                const int nt = (t == 8) ? 0 : t + 1;
                const uint32_t wb = sbW + ((s + 1) & 1) * W_PLANE_B;
                const uint32_t mb = sb + 16 + ((s + 1) & 1) * 8;
                MBARRIER_EXPECT_TX(mb, W_PLANE_B);
                TMA_LOAD_3D(wb, &mWh, nc * 32, n0, nt, mb);
            }
            if (t == 0) {
                if (tid == 0 && c < 7) {
                    const uint32_t ab2 = sbD + ((c + 1) & 1) * A_PLANE_B;
                    const uint32_t mb  = sb + ((c + 1) & 1) * 8;
                    MBARRIER_EXPECT_TX(mb, A_PLANE_B);          // 21760
                    TMA_LOAD_2D(ab2,           &mA, (c + 1) * 32, pixBase,           mb);
                    TMA_LOAD_2D(ab2 + A_BOX_B, &mA, (c + 1) * 32, pixBase + A_BOX_H, mb);
                }
                if (c & 1) { MBARRIER_WAIT_PARITY(sb + 8, phA1); phA1 ^= 1; }
                else       { MBARRIER_WAIT_PARITY(sb + 0, phA0); phA0 ^= 1; }
            }
            if (s & 1) { MBARRIER_WAIT_PARITY(sb + 24, phW1); phW1 ^= 1; }
            else       { MBARRIER_WAIT_PARITY(sb + 16, phW0); phW0 ^= 1; }

            // ---- compute tap t on chunk c ----
            const uint32_t Wb   = sbW + (s & 1) * W_PLANE_B;
            const uint32_t Aofs = (uint32_t)(((t / 3) * 66 + (t % 3)) * ROWB);
            #pragma unroll
            for (int ks = 0; ks < 2; ++ks) {
                uint32_t a0[4], a1r[4];
                LDSM4(a0,  Ab + Aofs + a_base[0] + ks * 32);
                LDSM4(a1r, Ab + Aofs + a_base[1] + ks * 32);
                #pragma unroll
                for (int nf = 0; nf < 4; ++nf) {
                    uint32_t bh[4];
                    LDSM4(bh, Wb + b_off[nf] + ks * 32);
                    MMA16816(acc[0][nf * 2],     a0,  bh[0], bh[1]);
                    MMA16816(acc[0][nf * 2 + 1], a0,  bh[2], bh[3]);
                    MMA16816(acc[1][nf * 2],     a1r, bh[0], bh[1]);
                    MMA16816(acc[1][nf * 2 + 1], a1r, bh[2], bh[3]);
                }
            }
            __syncthreads();
        }
    }

    // ---- epilogue ----
    const float ns = nscale[0];
    const float* __restrict__ dm = (CONV ? g_d2 : g_d1) + b * NTOT;
    const int q2 = (lane & 3) * 2;
    const int rr = lane >> 2;

    #pragma unroll
    for (int mf = 0; mf < 2; ++mf) {
        #pragma unroll
        for (int hf = 0; hf < 2; ++hf) {
            const int ml = wm * 32 + mf * 16 + rr + hf * 8;    // 0..127
            const int h  = R + (ml >> 6);
            const int w  = ml & 63;
            const float nz = noise[((size_t)b * H_SZ + h) * W_SZ + w] * ns;
            #pragma unroll
            for (int nf = 0; nf < 8; ++nf) {
                const int co = n0 + wn * 64 + nf * 8 + q2;
                float v0 = acc[mf][nf][hf * 2]     * dm[co]     + nz + bias[co];
                float v1 = acc[mf][nf][hf * 2 + 1] * dm[co + 1] + nz + bias[co + 1];
                v0 = (v0 > 0.f) ? v0 : 0.2f * v0;
                v1 = (v1 > 0.f) ? v1 : 0.2f * v1;
                if (CONV == 0) {
                    const float m0 = v0 * g_s2[b * CIN + co];
                    const float m1 = v1 * g_s2[b * CIN + co + 1];
                    const size_t o = ((size_t)(b * PW + h + 1) * PW + (w + 1)) * CIN + co;
                    *reinterpret_cast<__half2*>(g_x2p + o) =
                        __halves2half2(__float2half_rn(m0), __float2half_rn(m1));
                } else {
                    const int sh = co >> 8, sw = (co >> 7) & 1, c2 = co & 127;
                    float2 vv = make_float2(v0, v1);
                    *reinterpret_cast<float2*>(
                        outp + (((size_t)(b * 128 + 2 * h + sh)) * 128 + (2 * w + sw)) * 128 + c2) = vv;
                }
            }
        }
    }
}

// ---------------------------------------------------------------------------
// host
// ---------------------------------------------------------------------------
typedef CUresult (*PFN_tmap)(CUtensorMap*, CUtensorMapDataType, cuuint32_t, void*,
                             const cuuint64_t*, const cuuint64_t*, const cuuint32_t*,
                             const cuuint32_t*, CUtensorMapInterleave, CUtensorMapSwizzle,
                             CUtensorMapL2promotion, CUtensorMapFloatOOBfill);

static void encA(PFN_tmap fn, CUtensorMap* m, void* ptr)
{
    cuuint64_t dims[2]    = {CIN, NPIX};
    cuuint64_t strides[1] = {CIN * 2};
    cuuint32_t box[2]     = {40, A_BOX_H};
    cuuint32_t es[2]      = {1, 1};
    fn(m, CU_TENSOR_MAP_DATA_TYPE_FLOAT16, 2, ptr, dims, strides, box, es,
       CU_TENSOR_MAP_INTERLEAVE_NONE, CU_TENSOR_MAP_SWIZZLE_NONE,
       CU_TENSOR_MAP_L2_PROMOTION_L2_128B, CU_TENSOR_MAP_FLOAT_OOB_FILL_NONE);
}

static void encW(PFN_tmap fn, CUtensorMap* m, void* ptr, uint64_t ntot)
{
    cuuint64_t dims[3]    = {CIN, ntot, 9};
    cuuint64_t strides[2] = {CIN * 2, ntot * CIN * 2};
    cuuint32_t box[3]     = {40, 128, 1};
    cuuint32_t es[3]      = {1, 1, 1};
    fn(m, CU_TENSOR_MAP_DATA_TYPE_FLOAT16, 3, ptr, dims, strides, box, es,
       CU_TENSOR_MAP_INTERLEAVE_NONE, CU_TENSOR_MAP_SWIZZLE_NONE,
       CU_TENSOR_MAP_L2_PROMOTION_L2_128B, CU_TENSOR_MAP_FLOAT_OOB_FILL_NONE);
}

extern "C" void kernel_launch(void* const* d_in, const int* in_sizes, int n_in,
                              void* d_out, int out_size)
{
    const float* x    = (const float*)d_in[0];
    const float* w    = (const float*)d_in[1];
    const float* a1w  = (const float*)d_in[2];
    const float* a1b  = (const float*)d_in[3];
    const float* k1   = (const float*)d_in[4];
    const float* ns1  = (const float*)d_in[5];
    const float* b1   = (const float*)d_in[6];
    const float* a2w  = (const float*)d_in[7];
    const float* a2b  = (const float*)d_in[8];
    const float* k2   = (const float*)d_in[9];
    const float* ns2  = (const float*)d_in[10];
    const float* b2   = (const float*)d_in[11];
    const float* noi1 = (const float*)d_in[12];
    const float* noi2 = (const float*)d_in[13];
    float* outp = (float*)d_out;

    void* sym = nullptr;
    cudaDriverEntryPointQueryResult qres;
    cudaGetDriverEntryPoint("cuTensorMapEncodeTiled", &sym, cudaEnableDefault, &qres);
    PFN_tmap enc = (PFN_tmap)sym;

    void *pxp, *px2p, *pw1h, *pw2h;
    cudaGetSymbolAddress(&pxp,  g_xp);   cudaGetSymbolAddress(&px2p, g_x2p);
    cudaGetSymbolAddress(&pw1h, g_w1h);  cudaGetSymbolAddress(&pw2h, g_w2h);

    CUtensorMap mA1, mA2, mW1h, mW2h;
    encA(enc, &mA1, pxp);
    encA(enc, &mA2, px2p);
    encW(enc, &mW1h, pw1h, N1);
    encW(enc, &mW2h, pw2h, N2);

    cudaFuncSetAttribute(conv_mma<0>, cudaFuncAttributeMaxDynamicSharedMemorySize, SMEM_TOTAL);
    cudaFuncSetAttribute(conv_mma<1>, cudaFuncAttributeMaxDynamicSharedMemorySize, SMEM_TOTAL);

    // prep
    { dim3 g(B_SZ, 2);  style_all<<<g, CIN>>>(w, a1w, a1b, a2w, a2b); }
    { dim3 g(6, B_SZ);  demod_all<<<g, 128>>>(k1, k2); }
    { dim3 g((9 * N2 * 128 + 255) / 256, 2); wsplit_all<<<g, 256>>>(k1, k2); }
    pad_kernel<<<NPIX / 4, 256>>>(x);

    // conv1: xp -> x2p (epilogue multiplies by s2, single fp16 plane)
    {
        dim3 grid(N1 / 128, 512);
        conv_mma<0><<<grid, 256, SMEM_TOTAL>>>(mA1, mW1h, noi1, ns1, b1, nullptr);
    }
    // conv2: x2p -> d_out (pixel shuffled)
    {
        dim3 grid(N2 / 128, 512);
        conv_mma<1><<<grid, 256, SMEM_TOTAL>>>(mA2, mW2h, noi2, ns2, b2, outp);
    }
}

// round 9
// speedup vs baseline: 11.8073x; 1.0226x over previous
#include <cuda_runtime.h>
#include <cuda.h>
#include <cuda_fp16.h>
#include <cstdint>

// ---------------------------------------------------------------------------
// SynthesisBlock via mma.sync (HMMA), TMA bulk-tensor producers.
// R9 = R8 with per-stage __syncthreads replaced by empty-mbarrier recycling
// (consumers never block on each other) and W triple-buffered with a 2-stage
// TMA prefetch lead. Math identical to R8.
// ---------------------------------------------------------------------------
#define B_SZ 16
#define H_SZ 64
#define W_SZ 64
#define CIN  256
#define N1   256
#define N2   512
#define WDIM 128
#define PW   66          // padded H/W
#define NPIX (B_SZ * PW * PW)

// ---- device scratch ----
__device__ float g_s1[B_SZ * CIN];
__device__ float g_s2[B_SZ * CIN];
__device__ float g_d1[B_SZ * N1];
__device__ float g_d2[B_SZ * N2];
__device__ __half g_xp [NPIX * CIN];     // conv1 input, modulated by s1
__device__ __half g_x2p[NPIX * CIN];     // conv2 input (h * s2)
__device__ __half g_w1h[9 * N1 * CIN];   // [tap][n][ci]
__device__ __half g_w2h[9 * N2 * CIN];

// ---------------------------------------------------------------------------
// low-level helpers
// ---------------------------------------------------------------------------
__device__ __forceinline__ uint32_t smem_to_u32(const void* p) {
    uint32_t a;
    asm("{ .reg .u64 t; cvta.to.shared.u64 t, %1; cvt.u32.u64 %0, t; }" : "=r"(a) : "l"(p));
    return a;
}

#define MBARRIER_INIT(addr, count) \
    asm volatile("mbarrier.init.shared.b64 [%0], %1;" :: "r"((uint32_t)(addr)), "r"((uint32_t)(count)) : "memory")

#define MBARRIER_EXPECT_TX(addr, tx) \
    asm volatile("mbarrier.arrive.expect_tx.shared.b64 _, [%0], %1;" :: "r"((uint32_t)(addr)), "r"((uint32_t)(tx)) : "memory")

#define MBARRIER_ARRIVE(addr) \
    asm volatile("mbarrier.arrive.shared.b64 _, [%0];" :: "r"((uint32_t)(addr)) : "memory")

#define MBARRIER_WAIT_PARITY(mbar_smem_addr, phase_parity) do { \
    uint32_t _mbar = (uint32_t)(mbar_smem_addr); \
    uint32_t _parity = (uint32_t)(phase_parity); \
    uint32_t _done; \
    asm volatile( \
        "{\n\t.reg .pred p;\n\t" \
        "mbarrier.try_wait.parity.acquire.cta.shared::cta.b64 p, [%1], %2;\n\t" \
        "selp.b32 %0, 1, 0, p;\n\t}" \
        : "=r"(_done) : "r"(_mbar), "r"(_parity) : "memory"); \
    if (!_done) { \
        asm volatile( \
            "{\n\t.reg .pred P1;\n\t" \
            "WAIT_LOOP_%=:\n\t" \
            "mbarrier.try_wait.parity.acquire.cta.shared::cta.b64 P1, [%0], %1, 0x989680;\n\t" \
            "@P1 bra.uni WAIT_DONE_%=;\n\t" \
            "bra.uni WAIT_LOOP_%=;\n\t" \
            "WAIT_DONE_%=:\n\t}" \
            :: "r"(_mbar), "r"(_parity) : "memory"); \
    } \
} while(0)

// Relaxed wait: producer-side only (post-wait accesses are async-proxy TMA).
#define MBARRIER_WAIT_PARITY_RELAXED(mbar_smem_addr, phase_parity) do { \
    uint32_t _mbar = (uint32_t)(mbar_smem_addr); \
    uint32_t _parity = (uint32_t)(phase_parity); \
    uint32_t _done; \
    asm volatile( \
        "{\n\t.reg .pred p;\n\t" \
        "mbarrier.try_wait.parity.relaxed.cta.shared::cta.b64 p, [%1], %2, 0x989680;\n\t" \
        "selp.b32 %0, 1, 0, p;\n\t}" \
        : "=r"(_done) : "r"(_mbar), "r"(_parity) : "memory"); \
    if (!_done) { \
        asm volatile( \
            "{\n\t.reg .pred P1;\n\t" \
            "WAIT_LOOP_%=:\n\t" \
            "mbarrier.try_wait.parity.relaxed.cta.shared::cta.b64 P1, [%0], %1, 0x989680;\n\t" \
            "@P1 bra.uni WAIT_DONE_%=;\n\t" \
            "bra.uni WAIT_LOOP_%=;\n\t" \
            "WAIT_DONE_%=:\n\t}" \
            :: "r"(_mbar), "r"(_parity) : "memory"); \
    } \
} while(0)

#define TMA_LOAD_2D(smem_addr, tensor_map, cx, cy, mbar) \
    asm volatile( \
        "cp.async.bulk.tensor.2d.shared::cta.global.tile.mbarrier::complete_tx::bytes " \
        "[%0], [%1, {%2, %3}], [%4];" \
        :: "r"((uint32_t)(smem_addr)), "l"(tensor_map), \
           "r"((int32_t)(cx)), "r"((int32_t)(cy)), "r"((uint32_t)(mbar)) : "memory")

#define TMA_LOAD_3D(smem_addr, tensor_map, cx, cy, cz, mbar) \
    asm volatile( \
        "cp.async.bulk.tensor.3d.shared::cta.global.tile.mbarrier::complete_tx::bytes " \
        "[%0], [%1, {%2, %3, %4}], [%5];" \
        :: "r"((uint32_t)(smem_addr)), "l"(tensor_map), \
           "r"((int32_t)(cx)), "r"((int32_t)(cy)), "r"((int32_t)(cz)), \
           "r"((uint32_t)(mbar)) : "memory")

#define LDSM4(r, addr) \
    asm volatile("ldmatrix.sync.aligned.m8n8.x4.shared.b16 {%0,%1,%2,%3}, [%4];" \
        : "=r"((r)[0]), "=r"((r)[1]), "=r"((r)[2]), "=r"((r)[3]) : "r"(addr))

#define MMA16816(d, a, b0_, b1_) \
    asm volatile("mma.sync.aligned.m16n8k16.row.col.f32.f16.f16.f32 " \
        "{%0,%1,%2,%3}, {%4,%5,%6,%7}, {%8,%9}, {%0,%1,%2,%3};" \
        : "+f"((d)[0]), "+f"((d)[1]), "+f"((d)[2]), "+f"((d)[3]) \
        : "r"((a)[0]), "r"((a)[1]), "r"((a)[2]), "r"((a)[3]), "r"(b0_), "r"(b1_))

// ---------------------------------------------------------------------------
// prep 1: styles
// ---------------------------------------------------------------------------
__global__ void style_all(const float* __restrict__ w,
                          const float* __restrict__ a1w, const float* __restrict__ a1b,
                          const float* __restrict__ a2w, const float* __restrict__ a2b)
{
    int b = blockIdx.x, ci = threadIdx.x, which = blockIdx.y;
    const float* aw = which ? a2w : a1w;
    const float* ab = which ? a2b : a1b;
    float sum = ab[ci];
    const float* wr = w + b * WDIM;
    #pragma unroll 8
    for (int k = 0; k < WDIM; ++k) sum += wr[k] * aw[k * CIN + ci];
    (which ? g_s2 : g_s1)[b * CIN + ci] = sum;
}

// ---------------------------------------------------------------------------
// prep 2: demod (ksq fused)
// ---------------------------------------------------------------------------
__global__ void demod_all(const float* __restrict__ k1, const float* __restrict__ k2)
{
    const int blkx = blockIdx.x;
    const int conv = (blkx >= 2);
    const int NT   = conv ? N2 : N1;
    const int co   = (conv ? (blkx - 2) : blkx) * 128 + threadIdx.x;
    const int b    = blockIdx.y;
    const float* kern = conv ? k2 : k1;
    const float* st   = conv ? g_s2 : g_s1;

    __shared__ float ssq[CIN];
    for (int i = threadIdx.x; i < CIN; i += 128) {
        float s = st[b * CIN + i];
        ssq[i] = s * s;
    }
    __syncthreads();

    float acc = 0.f;
    for (int ci = 0; ci < CIN; ++ci) {
        float kv = 0.f;
        #pragma unroll
        for (int p = 0; p < 9; ++p) {
            float v = kern[((size_t)p * CIN + ci) * NT + co];
            kv += v * v;
        }
        acc += ssq[ci] * kv;
    }
    (conv ? g_d2 : g_d1)[b * NT + co] = rsqrtf(acc + 1e-8f);
}

// ---------------------------------------------------------------------------
// prep 3: weight transpose + fp16 round, ci-fastest (coalesced stores)
// ---------------------------------------------------------------------------
__global__ void wsplit_all(const float* __restrict__ k1, const float* __restrict__ k2)
{
    const int conv = blockIdx.y;
    const int NT   = conv ? N2 : N1;
    const int idx  = blockIdx.x * blockDim.x + threadIdx.x;   // over 9*NT*128
    if (idx >= 9 * NT * 128) return;
    const int g   = idx & 127;              // ci pair index
    const int n   = (idx >> 7) % NT;
    const int tap = (idx >> 7) / NT;
    const int ci  = g * 2;
    const float* kern = conv ? k2 : k1;
    const float v0 = kern[((size_t)(tap * CIN + ci))     * NT + n];
    const float v1 = kern[((size_t)(tap * CIN + ci + 1)) * NT + n];
    const size_t o = ((size_t)tap * NT + n) * CIN + ci;
    const __half2 hv = __halves2half2(__float2half_rn(v0), __float2half_rn(v1));
    if (conv == 0) *reinterpret_cast<__half2*>(g_w1h + o) = hv;
    else           *reinterpret_cast<__half2*>(g_w2h + o) = hv;
}

// ---------------------------------------------------------------------------
// prep 4: pad + modulate-by-s1 -> single fp16 plane; zero x2p borders.
// ---------------------------------------------------------------------------
__global__ void pad_kernel(const float* __restrict__ x)
{
    const int tid = threadIdx.x;
    const int pix = blockIdx.x * 4 + (tid >> 6);     // 0 .. NPIX-1
    const int ci  = (tid & 63) << 2;
    const int b  = pix / (PW * PW);
    const int r  = pix % (PW * PW);
    const int hp = r / PW, wp = r % PW;
    const bool interior = (hp >= 1) && (hp <= H_SZ) && (wp >= 1) && (wp <= W_SZ);

    uint2 packed = make_uint2(0u, 0u);
    if (interior) {
        const float4 v = *reinterpret_cast<const float4*>(
            x + (((size_t)b * H_SZ + (hp - 1)) * W_SZ + (wp - 1)) * CIN + ci);
        const float4 s = *reinterpret_cast<const float4*>(g_s1 + b * CIN + ci);
        __half2 p0 = __halves2half2(__float2half_rn(v.x * s.x), __float2half_rn(v.y * s.y));
        __half2 p1 = __halves2half2(__float2half_rn(v.z * s.z), __float2half_rn(v.w * s.w));
        packed.x = *reinterpret_cast<uint32_t*>(&p0);
        packed.y = *reinterpret_cast<uint32_t*>(&p1);
    }
    const size_t o = (size_t)pix * CIN + ci;
    *reinterpret_cast<uint2*>(g_xp + o) = packed;
    if (!interior)
        *reinterpret_cast<uint2*>(g_x2p + o) = make_uint2(0u, 0u);
}

// ---------------------------------------------------------------------------
// conv GEMM. CTA: 128 pixels (2 image rows) x 128 output channels.
// 256 threads, 8 warps (4m x 2n), warp tile 32x64, 2 CTAs/SM.
// Pipeline: per-warp mbarrier recycling (no per-stage __syncthreads).
//   A: slab of 264 pixel rows per ci-chunk (2 boxes of 136 rows), 2 buffers,
//      empty-barrier (count 8) recycling; reused by all 9 taps per chunk.
//   W: 128co x 32ci per tap-stage, 3 buffers, 2-stage TMA prefetch lead,
//      empty-barrier (count 8) recycling.
// MMA: single pass A*W per tap.
// Barriers @ sb: AF0=0 AF1=8 WF0=16 WF1=24 WF2=32 AE0=40 AE1=48 WE0=56 WE1=64 WE2=72
// ---------------------------------------------------------------------------
#define ROWB       80
#define A_BOX_H    136
#define A_BOX_B    (A_BOX_H * ROWB)       // 10880 = 85*128
#define A_PLANE_B  (2 * A_BOX_B)          // 21760
#define W_PLANE_B  (128 * ROWB)           // 10240
#define SM_CTRL    1024
#define SMEM_TOTAL (SM_CTRL + 2 * A_PLANE_B + 3 * W_PLANE_B)   // 75264

template<int CONV>
__global__ void __launch_bounds__(256, 2)
conv_mma(const __grid_constant__ CUtensorMap mA,
         const __grid_constant__ CUtensorMap mWh,
         const float* __restrict__ noise,
         const float* __restrict__ nscale,
         const float* __restrict__ bias,
         float* __restrict__ outp)
{
    constexpr int NTOT = CONV ? N2 : N1;
    extern __shared__ __align__(128) char smem[];
    const uint32_t sb  = smem_to_u32(smem);
    const uint32_t sbD = sb + SM_CTRL;
    const uint32_t sbW = sbD + 2 * A_PLANE_B;

    const int tid  = threadIdx.x;
    const int lane = tid & 31;
    const int warp = tid >> 5;
    const int wm   = warp >> 1;          // 0..3  (32-row m slice)
    const int wn   = warp & 1;           // 0..1  (64-col n slice)

    const int mtile = blockIdx.y;        // 0..511
    const int b  = mtile >> 5;
    const int R  = (mtile & 31) << 1;    // first output image row
    const int n0 = blockIdx.x << 7;
    const int pixBase = (b * PW + R) * PW;

    if (tid == 0) {
        MBARRIER_INIT(sb + 0, 1);  MBARRIER_INIT(sb + 8, 1);    // A full
        MBARRIER_INIT(sb + 16, 1); MBARRIER_INIT(sb + 24, 1); MBARRIER_INIT(sb + 32, 1); // W full
        MBARRIER_INIT(sb + 40, 8); MBARRIER_INIT(sb + 48, 8);   // A empty (8 warps)
        MBARRIER_INIT(sb + 56, 8); MBARRIER_INIT(sb + 64, 8); MBARRIER_INIT(sb + 72, 8); // W empty
    }
    __syncthreads();

    // ---- ldmatrix fragment smem offsets (relative to buffer base) ----
    uint32_t a_base[2];
    #pragma unroll
    for (int mf = 0; mf < 2; ++mf) {
        const int m    = wm * 32 + mf * 16 + (lane & 15);
        const int srow = (m >> 6) * 66 + (m & 63);      // slab pixel-row (tap 0)
        a_base[mf] = (uint32_t)(srow * ROWB + ((lane >> 4) << 4));
    }
    uint32_t b_off[4];
    #pragma unroll
    for (int nf = 0; nf < 4; ++nf)
        b_off[nf] = (uint32_t)((wn * 64 + nf * 16 + (lane & 7) + ((lane >> 4) << 3)) * ROWB
                               + (((lane >> 3) & 1) << 4));

    float acc[2][8][4];
    #pragma unroll
    for (int i = 0; i < 2; ++i)
        #pragma unroll
        for (int j = 0; j < 8; ++j)
            #pragma unroll
            for (int k = 0; k < 4; ++k) acc[i][j][k] = 0.f;

    // ---- prologue: A chunk 0 + W stages 0,1 ----
    if (tid == 0) {
        MBARRIER_EXPECT_TX(sb + 0, A_PLANE_B);
        TMA_LOAD_2D(sbD,           &mA, 0, pixBase,           sb + 0);
        TMA_LOAD_2D(sbD + A_BOX_B, &mA, 0, pixBase + A_BOX_H, sb + 0);
        MBARRIER_EXPECT_TX(sb + 16, W_PLANE_B);
        TMA_LOAD_3D(sbW, &mWh, 0, n0, 0, sb + 16);
        MBARRIER_EXPECT_TX(sb + 24, W_PLANE_B);
        TMA_LOAD_3D(sbW + W_PLANE_B, &mWh, 0, n0, 1, sb + 24);
    }

    // ---- main loop: 8 chunks x 9 taps; s = c*9 + t ----
    int s = 0, s3r = 0, s3q = 0;          // s3r = s%3, s3q = s/3
    #pragma unroll 1
    for (int c = 0; c < 8; ++c) {
        const uint32_t Ab = sbD + (c & 1) * A_PLANE_B;
        #pragma unroll 1
        for (int t = 0; t < 9; ++t, ++s) {
            if (tid == 0) {
                const int ws = s + 2;                   // W prefetch, 2-stage lead
                if (ws < 72) {
                    const int wb = ws % 3;
                    if (ws >= 3)
                        MBARRIER_WAIT_PARITY_RELAXED(sb + 56 + wb * 8, ((ws / 3) - 1) & 1);
                    MBARRIER_EXPECT_TX(sb + 16 + wb * 8, W_PLANE_B);
                    TMA_LOAD_3D(sbW + wb * W_PLANE_B, &mWh, (ws / 9) * 32, n0, ws % 9,
                                sb + 16 + wb * 8);
                }
                if (t == 0 && c < 7) {                  // A prefetch, chunk c+1
                    const int nc = c + 1;
                    const int ab = nc & 1;
                    if (nc >= 2)
                        MBARRIER_WAIT_PARITY_RELAXED(sb + 40 + ab * 8, ((nc >> 1) - 1) & 1);
                    const uint32_t ab2 = sbD + ab * A_PLANE_B;
                    MBARRIER_EXPECT_TX(sb + ab * 8, A_PLANE_B);
                    TMA_LOAD_2D(ab2,           &mA, nc * 32, pixBase,           sb + ab * 8);
                    TMA_LOAD_2D(ab2 + A_BOX_B, &mA, nc * 32, pixBase + A_BOX_H, sb + ab * 8);
                }
            }
            if (t == 0)
                MBARRIER_WAIT_PARITY(sb + (c & 1) * 8, (c >> 1) & 1);
            MBARRIER_WAIT_PARITY(sb + 16 + s3r * 8, s3q & 1);

            // ---- compute tap t on chunk c ----
            const uint32_t Wb   = sbW + s3r * W_PLANE_B;
            const uint32_t Aofs = (uint32_t)(((t / 3) * 66 + (t % 3)) * ROWB);
            #pragma unroll
            for (int ks = 0; ks < 2; ++ks) {
                uint32_t a0[4], a1r[4];
                LDSM4(a0,  Ab + Aofs + a_base[0] + ks * 32);
                LDSM4(a1r, Ab + Aofs + a_base[1] + ks * 32);
                #pragma unroll
                for (int nf = 0; nf < 4; ++nf) {
                    uint32_t bh[4];
                    LDSM4(bh, Wb + b_off[nf] + ks * 32);
                    MMA16816(acc[0][nf * 2],     a0,  bh[0], bh[1]);
                    MMA16816(acc[0][nf * 2 + 1], a0,  bh[2], bh[3]);
                    MMA16816(acc[1][nf * 2],     a1r, bh[0], bh[1]);
                    MMA16816(acc[1][nf * 2 + 1], a1r, bh[2], bh[3]);
                }
            }
            if (lane == 0) {
                MBARRIER_ARRIVE(sb + 56 + s3r * 8);            // W buffer consumed
                if (t == 8)
                    MBARRIER_ARRIVE(sb + 40 + (c & 1) * 8);    // A chunk consumed
            }
            if (++s3r == 3) { s3r = 0; ++s3q; }
        }
    }

    // ---- epilogue ----
    const float ns = nscale[0];
    const float* __restrict__ dm = (CONV ? g_d2 : g_d1) + b * NTOT;
    const int q2 = (lane & 3) * 2;
    const int rr = lane >> 2;

    #pragma unroll
    for (int mf = 0; mf < 2; ++mf) {
        #pragma unroll
        for (int hf = 0; hf < 2; ++hf) {
            const int ml = wm * 32 + mf * 16 + rr + hf * 8;    // 0..127
            const int h  = R + (ml >> 6);
            const int w  = ml & 63;
            const float nz = noise[((size_t)b * H_SZ + h) * W_SZ + w] * ns;
            #pragma unroll
            for (int nf = 0; nf < 8; ++nf) {
                const int co = n0 + wn * 64 + nf * 8 + q2;
                float v0 = acc[mf][nf][hf * 2]     * dm[co]     + nz + bias[co];
                float v1 = acc[mf][nf][hf * 2 + 1] * dm[co + 1] + nz + bias[co + 1];
                v0 = (v0 > 0.f) ? v0 : 0.2f * v0;
                v1 = (v1 > 0.f) ? v1 : 0.2f * v1;
                if (CONV == 0) {
                    const float m0 = v0 * g_s2[b * CIN + co];
                    const float m1 = v1 * g_s2[b * CIN + co + 1];
                    const size_t o = ((size_t)(b * PW + h + 1) * PW + (w + 1)) * CIN + co;
                    *reinterpret_cast<__half2*>(g_x2p + o) =
                        __halves2half2(__float2half_rn(m0), __float2half_rn(m1));
                } else {
                    const int sh = co >> 8, sw = (co >> 7) & 1, c2 = co & 127;
                    float2 vv = make_float2(v0, v1);
                    *reinterpret_cast<float2*>(
                        outp + (((size_t)(b * 128 + 2 * h + sh)) * 128 + (2 * w + sw)) * 128 + c2) = vv;
                }
            }
        }
    }
}

// ---------------------------------------------------------------------------
// host
// ---------------------------------------------------------------------------
typedef CUresult (*PFN_tmap)(CUtensorMap*, CUtensorMapDataType, cuuint32_t, void*,
                             const cuuint64_t*, const cuuint64_t*, const cuuint32_t*,
                             const cuuint32_t*, CUtensorMapInterleave, CUtensorMapSwizzle,
                             CUtensorMapL2promotion, CUtensorMapFloatOOBfill);

static void encA(PFN_tmap fn, CUtensorMap* m, void* ptr)
{
    cuuint64_t dims[2]    = {CIN, NPIX};
    cuuint64_t strides[1] = {CIN * 2};
    cuuint32_t box[2]     = {40, A_BOX_H};
    cuuint32_t es[2]      = {1, 1};
    fn(m, CU_TENSOR_MAP_DATA_TYPE_FLOAT16, 2, ptr, dims, strides, box, es,
       CU_TENSOR_MAP_INTERLEAVE_NONE, CU_TENSOR_MAP_SWIZZLE_NONE,
       CU_TENSOR_MAP_L2_PROMOTION_L2_128B, CU_TENSOR_MAP_FLOAT_OOB_FILL_NONE);
}

static void encW(PFN_tmap fn, CUtensorMap* m, void* ptr, uint64_t ntot)
{
    cuuint64_t dims[3]    = {CIN, ntot, 9};
    cuuint64_t strides[2] = {CIN * 2, ntot * CIN * 2};
    cuuint32_t box[3]     = {40, 128, 1};
    cuuint32_t es[3]      = {1, 1, 1};
    fn(m, CU_TENSOR_MAP_DATA_TYPE_FLOAT16, 3, ptr, dims, strides, box, es,
       CU_TENSOR_MAP_INTERLEAVE_NONE, CU_TENSOR_MAP_SWIZZLE_NONE,
       CU_TENSOR_MAP_L2_PROMOTION_L2_128B, CU_TENSOR_MAP_FLOAT_OOB_FILL_NONE);
}

extern "C" void kernel_launch(void* const* d_in, const int* in_sizes, int n_in,
                              void* d_out, int out_size)
{
    const float* x    = (const float*)d_in[0];
    const float* w    = (const float*)d_in[1];
    const float* a1w  = (const float*)d_in[2];
    const float* a1b  = (const float*)d_in[3];
    const float* k1   = (const float*)d_in[4];
    const float* ns1  = (const float*)d_in[5];
    const float* b1   = (const float*)d_in[6];
    const float* a2w  = (const float*)d_in[7];
    const float* a2b  = (const float*)d_in[8];
    const float* k2   = (const float*)d_in[9];
    const float* ns2  = (const float*)d_in[10];
    const float* b2   = (const float*)d_in[11];
    const float* noi1 = (const float*)d_in[12];
    const float* noi2 = (const float*)d_in[13];
    float* outp = (float*)d_out;

    void* sym = nullptr;
    cudaDriverEntryPointQueryResult qres;
    cudaGetDriverEntryPoint("cuTensorMapEncodeTiled", &sym, cudaEnableDefault, &qres);
    PFN_tmap enc = (PFN_tmap)sym;

    void *pxp, *px2p, *pw1h, *pw2h;
    cudaGetSymbolAddress(&pxp,  g_xp);   cudaGetSymbolAddress(&px2p, g_x2p);
    cudaGetSymbolAddress(&pw1h, g_w1h);  cudaGetSymbolAddress(&pw2h, g_w2h);

    CUtensorMap mA1, mA2, mW1h, mW2h;
    encA(enc, &mA1, pxp);
    encA(enc, &mA2, px2p);
    encW(enc, &mW1h, pw1h, N1);
    encW(enc, &mW2h, pw2h, N2);

    cudaFuncSetAttribute(conv_mma<0>, cudaFuncAttributeMaxDynamicSharedMemorySize, SMEM_TOTAL);
    cudaFuncSetAttribute(conv_mma<1>, cudaFuncAttributeMaxDynamicSharedMemorySize, SMEM_TOTAL);

    // prep
    { dim3 g(B_SZ, 2);  style_all<<<g, CIN>>>(w, a1w, a1b, a2w, a2b); }
    { dim3 g(6, B_SZ);  demod_all<<<g, 128>>>(k1, k2); }
    { dim3 g((9 * N2 * 128 + 255) / 256, 2); wsplit_all<<<g, 256>>>(k1, k2); }
    pad_kernel<<<NPIX / 4, 256>>>(x);

    // conv1: xp -> x2p (epilogue multiplies by s2, single fp16 plane)
    {
        dim3 grid(N1 / 128, 512);
        conv_mma<0><<<grid, 256, SMEM_TOTAL>>>(mA1, mW1h, noi1, ns1, b1, nullptr);
    }
    // conv2: x2p -> d_out (pixel shuffled)
    {
        dim3 grid(N2 / 128, 512);
        conv_mma<1><<<grid, 256, SMEM_TOTAL>>>(mA2, mW2h, noi2, ns2, b2, outp);
    }
}

// round 10
// speedup vs baseline: 13.6274x; 1.1542x over previous
#include <cuda_runtime.h>
#include <cuda.h>
#include <cuda_fp16.h>
#include <cstdint>

// ---------------------------------------------------------------------------
// SynthesisBlock via mma.sync (HMMA), TMA bulk-tensor producers.
// R10 = R9 + (a) transpose-tiled wsplit (coalesced), (b) ksq precompute so
// demod stops re-reading kernels 16x, (c) W stages carry 2 taps per TMA
// (40 stages instead of 72). Math identical to R8/R9.
// ---------------------------------------------------------------------------
#define B_SZ 16
#define H_SZ 64
#define W_SZ 64
#define CIN  256
#define N1   256
#define N2   512
#define WDIM 128
#define PW   66          // padded H/W
#define NPIX (B_SZ * PW * PW)

// ---- device scratch ----
__device__ float g_s1[B_SZ * CIN];
__device__ float g_s2[B_SZ * CIN];
__device__ float g_d1[B_SZ * N1];
__device__ float g_d2[B_SZ * N2];
__device__ float g_ksq1[CIN * N1];
__device__ float g_ksq2[CIN * N2];
__device__ __half g_xp [NPIX * CIN];     // conv1 input, modulated by s1
__device__ __half g_x2p[NPIX * CIN];     // conv2 input (h * s2)
__device__ __half g_w1h[9 * N1 * CIN];   // [tap][n][ci]
__device__ __half g_w2h[9 * N2 * CIN];

// ---------------------------------------------------------------------------
// low-level helpers
// ---------------------------------------------------------------------------
__device__ __forceinline__ uint32_t smem_to_u32(const void* p) {
    uint32_t a;
    asm("{ .reg .u64 t; cvta.to.shared.u64 t, %1; cvt.u32.u64 %0, t; }" : "=r"(a) : "l"(p));
    return a;
}

#define MBARRIER_INIT(addr, count) \
    asm volatile("mbarrier.init.shared.b64 [%0], %1;" :: "r"((uint32_t)(addr)), "r"((uint32_t)(count)) : "memory")

#define MBARRIER_EXPECT_TX(addr, tx) \
    asm volatile("mbarrier.arrive.expect_tx.shared.b64 _, [%0], %1;" :: "r"((uint32_t)(addr)), "r"((uint32_t)(tx)) : "memory")

#define MBARRIER_ARRIVE(addr) \
    asm volatile("mbarrier.arrive.shared.b64 _, [%0];" :: "r"((uint32_t)(addr)) : "memory")

#define MBARRIER_WAIT_PARITY(mbar_smem_addr, phase_parity) do { \
    uint32_t _mbar = (uint32_t)(mbar_smem_addr); \
    uint32_t _parity = (uint32_t)(phase_parity); \
    uint32_t _done; \
    asm volatile( \
        "{\n\t.reg .pred p;\n\t" \
        "mbarrier.try_wait.parity.acquire.cta.shared::cta.b64 p, [%1], %2;\n\t" \
        "selp.b32 %0, 1, 0, p;\n\t}" \
        : "=r"(_done) : "r"(_mbar), "r"(_parity) : "memory"); \
    if (!_done) { \
        asm volatile( \
            "{\n\t.reg .pred P1;\n\t" \
            "WAIT_LOOP_%=:\n\t" \
            "mbarrier.try_wait.parity.acquire.cta.shared::cta.b64 P1, [%0], %1, 0x989680;\n\t" \
            "@P1 bra.uni WAIT_DONE_%=;\n\t" \
            "bra.uni WAIT_LOOP_%=;\n\t" \
            "WAIT_DONE_%=:\n\t}" \
            :: "r"(_mbar), "r"(_parity) : "memory"); \
    } \
} while(0)

// Relaxed wait: producer-side only (post-wait accesses are async-proxy TMA).
#define MBARRIER_WAIT_PARITY_RELAXED(mbar_smem_addr, phase_parity) do { \
    uint32_t _mbar = (uint32_t)(mbar_smem_addr); \
    uint32_t _parity = (uint32_t)(phase_parity); \
    uint32_t _done; \
    asm volatile( \
        "{\n\t.reg .pred p;\n\t" \
        "mbarrier.try_wait.parity.relaxed.cta.shared::cta.b64 p, [%1], %2, 0x989680;\n\t" \
        "selp.b32 %0, 1, 0, p;\n\t}" \
        : "=r"(_done) : "r"(_mbar), "r"(_parity) : "memory"); \
    if (!_done) { \
        asm volatile( \
            "{\n\t.reg .pred P1;\n\t" \
            "WAIT_LOOP_%=:\n\t" \
            "mbarrier.try_wait.parity.relaxed.cta.shared::cta.b64 P1, [%0], %1, 0x989680;\n\t" \
            "@P1 bra.uni WAIT_DONE_%=;\n\t" \
            "bra.uni WAIT_LOOP_%=;\n\t" \
            "WAIT_DONE_%=:\n\t}" \
            :: "r"(_mbar), "r"(_parity) : "memory"); \
    } \
} while(0)

#define TMA_LOAD_2D(smem_addr, tensor_map, cx, cy, mbar) \
    asm volatile( \
        "cp.async.bulk.tensor.2d.shared::cta.global.tile.mbarrier::complete_tx::bytes " \
        "[%0], [%1, {%2, %3}], [%4];" \
        :: "r"((uint32_t)(smem_addr)), "l"(tensor_map), \
           "r"((int32_t)(cx)), "r"((int32_t)(cy)), "r"((uint32_t)(mbar)) : "memory")

#define TMA_LOAD_3D(smem_addr, tensor_map, cx, cy, cz, mbar) \
    asm volatile( \
        "cp.async.bulk.tensor.3d.shared::cta.global.tile.mbarrier::complete_tx::bytes " \
        "[%0], [%1, {%2, %3, %4}], [%5];" \
        :: "r"((uint32_t)(smem_addr)), "l"(tensor_map), \
           "r"((int32_t)(cx)), "r"((int32_t)(cy)), "r"((int32_t)(cz)), \
           "r"((uint32_t)(mbar)) : "memory")

#define LDSM4(r, addr) \
    asm volatile("ldmatrix.sync.aligned.m8n8.x4.shared.b16 {%0,%1,%2,%3}, [%4];" \
        : "=r"((r)[0]), "=r"((r)[1]), "=r"((r)[2]), "=r"((r)[3]) : "r"(addr))

#define MMA16816(d, a, b0_, b1_) \
    asm volatile("mma.sync.aligned.m16n8k16.row.col.f32.f16.f16.f32 " \
        "{%0,%1,%2,%3}, {%4,%5,%6,%7}, {%8,%9}, {%0,%1,%2,%3};" \
        : "+f"((d)[0]), "+f"((d)[1]), "+f"((d)[2]), "+f"((d)[3]) \
        : "r"((a)[0]), "r"((a)[1]), "r"((a)[2]), "r"((a)[3]), "r"(b0_), "r"(b1_))

// ---------------------------------------------------------------------------
// prep 1: styles
// ---------------------------------------------------------------------------
__global__ void style_all(const float* __restrict__ w,
                          const float* __restrict__ a1w, const float* __restrict__ a1b,
                          const float* __restrict__ a2w, const float* __restrict__ a2b)
{
    int b = blockIdx.x, ci = threadIdx.x, which = blockIdx.y;
    const float* aw = which ? a2w : a1w;
    const float* ab = which ? a2b : a1b;
    float sum = ab[ci];
    const float* wr = w + b * WDIM;
    #pragma unroll 8
    for (int k = 0; k < WDIM; ++k) sum += wr[k] * aw[k * CIN + ci];
    (which ? g_s2 : g_s1)[b * CIN + ci] = sum;
}

// ---------------------------------------------------------------------------
// prep 2a: ksq[ci,co] = sum over 9 taps of kern^2 (coalesced along co)
// ---------------------------------------------------------------------------
__global__ void ksq_all(const float* __restrict__ k1, const float* __restrict__ k2)
{
    const int conv  = blockIdx.y;
    const int NT    = conv ? N2 : N1;
    const int total = CIN * NT;
    const int idx   = blockIdx.x * blockDim.x + threadIdx.x;   // = ci*NT + co
    if (idx >= total) return;
    const float* kern = conv ? k2 : k1;
    float s = 0.f;
    #pragma unroll
    for (int p = 0; p < 9; ++p) {
        float v = kern[(size_t)p * total + idx];
        s += v * v;
    }
    (conv ? g_ksq2 : g_ksq1)[idx] = s;
}

// ---------------------------------------------------------------------------
// prep 2b: demod from the small L2-resident ksq table
// ---------------------------------------------------------------------------
__global__ void demod_all()
{
    const int blkx = blockIdx.x;
    const int conv = (blkx >= 2);
    const int NT   = conv ? N2 : N1;
    const int co   = (conv ? (blkx - 2) : blkx) * 128 + threadIdx.x;
    const int b    = blockIdx.y;
    const float* st = conv ? g_s2 : g_s1;
    const float* kq = conv ? g_ksq2 : g_ksq1;

    __shared__ float ssq[CIN];
    for (int i = threadIdx.x; i < CIN; i += 128) {
        float s = st[b * CIN + i];
        ssq[i] = s * s;
    }
    __syncthreads();

    float acc = 0.f;
    #pragma unroll 8
    for (int ci = 0; ci < CIN; ++ci)
        acc += ssq[ci] * kq[ci * NT + co];
    (conv ? g_d2 : g_d1)[b * NT + co] = rsqrtf(acc + 1e-8f);
}

// ---------------------------------------------------------------------------
// prep 3: weight transpose + fp16 round via smem tile (coalesced both sides)
// block: 256 thr; tile = 32 ci x 64 n; grid (8 ci-tiles, n-tiles, 18=tapxconv)
// ---------------------------------------------------------------------------
__global__ void wsplit_all(const float* __restrict__ k1, const float* __restrict__ k2)
{
    const int conv = blockIdx.z / 9;
    const int tap  = blockIdx.z % 9;
    const int NT   = conv ? N2 : N1;
    if ((int)blockIdx.y * 64 >= NT) return;
    const int ci0 = blockIdx.x * 32;
    const int n0  = blockIdx.y * 64;
    const float* kern = conv ? k2 : k1;
    __half* dst = conv ? g_w2h : g_w1h;

    __shared__ __half tile[32][66];
    const int tid = threadIdx.x;
    const int tx  = tid & 63;           // n
    const int ty  = tid >> 6;           // ci sub 0..3
    #pragma unroll
    for (int i = 0; i < 8; ++i) {
        const int ci = i * 4 + ty;
        tile[ci][tx] = __float2half_rn(
            kern[((size_t)(tap * CIN + ci0 + ci)) * NT + n0 + tx]);
    }
    __syncthreads();

    const int cp = tid & 15;            // ci pair
    const int nn = tid >> 4;            // 0..15
    #pragma unroll
    for (int i = 0; i < 4; ++i) {
        const int n = i * 16 + nn;
        const __half2 hv = __halves2half2(tile[2 * cp][n], tile[2 * cp + 1][n]);
        *reinterpret_cast<__half2*>(
            dst + ((size_t)(tap * NT + n0 + n)) * CIN + ci0 + 2 * cp) = hv;
    }
}

// ---------------------------------------------------------------------------
// prep 4: pad + modulate-by-s1 -> single fp16 plane; zero x2p borders.
// ---------------------------------------------------------------------------
__global__ void pad_kernel(const float* __restrict__ x)
{
    const int tid = threadIdx.x;
    const int pix = blockIdx.x * 4 + (tid >> 6);     // 0 .. NPIX-1
    const int ci  = (tid & 63) << 2;
    const int b  = pix / (PW * PW);
    const int r  = pix % (PW * PW);
    const int hp = r / PW, wp = r % PW;
    const bool interior = (hp >= 1) && (hp <= H_SZ) && (wp >= 1) && (wp <= W_SZ);

    uint2 packed = make_uint2(0u, 0u);
    if (interior) {
        const float4 v = *reinterpret_cast<const float4*>(
            x + (((size_t)b * H_SZ + (hp - 1)) * W_SZ + (wp - 1)) * CIN + ci);
        const float4 s = *reinterpret_cast<const float4*>(g_s1 + b * CIN + ci);
        __half2 p0 = __halves2half2(__float2half_rn(v.x * s.x), __float2half_rn(v.y * s.y));
        __half2 p1 = __halves2half2(__float2half_rn(v.z * s.z), __float2half_rn(v.w * s.w));
        packed.x = *reinterpret_cast<uint32_t*>(&p0);
        packed.y = *reinterpret_cast<uint32_t*>(&p1);
    }
    const size_t o = (size_t)pix * CIN + ci;
    *reinterpret_cast<uint2*>(g_xp + o) = packed;
    if (!interior)
        *reinterpret_cast<uint2*>(g_x2p + o) = make_uint2(0u, 0u);
}

// ---------------------------------------------------------------------------
// conv GEMM. CTA: 128 pixels x 128 output channels. 256 thr, 8 warps (4m x 2n),
// warp tile 32x64, 2 CTAs/SM. Per-warp mbarrier recycling (no stage syncthreads).
//   A: 264-row slab per ci-chunk (2 boxes of 136 rows), 2 buffers.
//   W: TWO taps per stage (TMA box z=2; tap 9 zero-filled, never computed),
//      3 buffers, 2-stage prefetch lead. 40 stages total (8 chunks x 5).
// Barriers @ sb: AF0=0 AF1=8 WF0=16 WF1=24 WF2=32 AE0=40 AE1=48 WE0=56 WE1=64 WE2=72
// ---------------------------------------------------------------------------
#define ROWB       80
#define A_BOX_H    136
#define A_BOX_B    (A_BOX_H * ROWB)       // 10880 = 85*128
#define A_PLANE_B  (2 * A_BOX_B)          // 21760
#define W_PLANE_B  (128 * ROWB)           // 10240 (one tap)
#define W_STG_B    (2 * W_PLANE_B)        // 20480 (two taps)
#define SM_CTRL    1024
#define SMEM_TOTAL (SM_CTRL + 2 * A_PLANE_B + 3 * W_STG_B)   // 105984

template<int CONV>
__global__ void __launch_bounds__(256, 2)
conv_mma(const __grid_constant__ CUtensorMap mA,
         const __grid_constant__ CUtensorMap mWh,
         const float* __restrict__ noise,
         const float* __restrict__ nscale,
         const float* __restrict__ bias,
         float* __restrict__ outp)
{
    constexpr int NTOT = CONV ? N2 : N1;
    extern __shared__ __align__(128) char smem[];
    const uint32_t sb  = smem_to_u32(smem);
    const uint32_t sbD = sb + SM_CTRL;
    const uint32_t sbW = sbD + 2 * A_PLANE_B;

    const int tid  = threadIdx.x;
    const int lane = tid & 31;
    const int warp = tid >> 5;
    const int wm   = warp >> 1;          // 0..3  (32-row m slice)
    const int wn   = warp & 1;           // 0..1  (64-col n slice)

    const int mtile = blockIdx.y;        // 0..511
    const int b  = mtile >> 5;
    const int R  = (mtile & 31) << 1;    // first output image row
    const int n0 = blockIdx.x << 7;
    const int pixBase = (b * PW + R) * PW;

    if (tid == 0) {
        MBARRIER_INIT(sb + 0, 1);  MBARRIER_INIT(sb + 8, 1);    // A full
        MBARRIER_INIT(sb + 16, 1); MBARRIER_INIT(sb + 24, 1); MBARRIER_INIT(sb + 32, 1); // W full
        MBARRIER_INIT(sb + 40, 8); MBARRIER_INIT(sb + 48, 8);   // A empty (8 warps)
        MBARRIER_INIT(sb + 56, 8); MBARRIER_INIT(sb + 64, 8); MBARRIER_INIT(sb + 72, 8); // W empty
    }
    __syncthreads();

    // ---- ldmatrix fragment smem offsets (relative to buffer base) ----
    uint32_t a_base[2];
    #pragma unroll
    for (int mf = 0; mf < 2; ++mf) {
        const int m    = wm * 32 + mf * 16 + (lane & 15);
        const int srow = (m >> 6) * 66 + (m & 63);      // slab pixel-row (tap 0)
        a_base[mf] = (uint32_t)(srow * ROWB + ((lane >> 4) << 4));
    }
    uint32_t b_off[4];
    #pragma unroll
    for (int nf = 0; nf < 4; ++nf)
        b_off[nf] = (uint32_t)((wn * 64 + nf * 16 + (lane & 7) + ((lane >> 4) << 3)) * ROWB
                               + (((lane >> 3) & 1) << 4));

    float acc[2][8][4];
    #pragma unroll
    for (int i = 0; i < 2; ++i)
        #pragma unroll
        for (int j = 0; j < 8; ++j)
            #pragma unroll
            for (int k = 0; k < 4; ++k) acc[i][j][k] = 0.f;

    // ---- prologue: A chunk 0 + W stages 0,1 (taps 0-1, 2-3) ----
    if (tid == 0) {
        MBARRIER_EXPECT_TX(sb + 0, A_PLANE_B);
        TMA_LOAD_2D(sbD,           &mA, 0, pixBase,           sb + 0);
        TMA_LOAD_2D(sbD + A_BOX_B, &mA, 0, pixBase + A_BOX_H, sb + 0);
        MBARRIER_EXPECT_TX(sb + 16, W_STG_B);
        TMA_LOAD_3D(sbW, &mWh, 0, n0, 0, sb + 16);
        MBARRIER_EXPECT_TX(sb + 24, W_STG_B);
        TMA_LOAD_3D(sbW + W_STG_B, &mWh, 0, n0, 2, sb + 24);
    }

    // ---- main loop: 8 chunks x 5 double-tap stages; s = c*5 + u ----
    int s = 0, s3r = 0, s3q = 0;          // s3r = s%3, s3q = (s/3)&1
    #pragma unroll 1
    for (int c = 0; c < 8; ++c) {
        const uint32_t Ab = sbD + (c & 1) * A_PLANE_B;
        #pragma unroll 1
        for (int u = 0; u < 5; ++u, ++s) {
            if (tid == 0) {
                const int ws = s + 2;                   // W prefetch, 2-stage lead
                if (ws < 40) {
                    const int wq = ws / 3, wb = ws - wq * 3;
                    if (ws >= 3)
                        MBARRIER_WAIT_PARITY_RELAXED(sb + 56 + wb * 8, (wq - 1) & 1);
                    MBARRIER_EXPECT_TX(sb + 16 + wb * 8, W_STG_B);
                    TMA_LOAD_3D(sbW + wb * W_STG_B, &mWh, (ws / 5) * 32, n0,
                                (ws % 5) * 2, sb + 16 + wb * 8);
                }
                if (u == 0 && c < 7) {                  // A prefetch, chunk c+1
                    const int nc = c + 1;
                    const int ab = nc & 1;
                    if (nc >= 2)
                        MBARRIER_WAIT_PARITY_RELAXED(sb + 40 + ab * 8, ((nc >> 1) - 1) & 1);
                    const uint32_t ab2 = sbD + ab * A_PLANE_B;
                    MBARRIER_EXPECT_TX(sb + ab * 8, A_PLANE_B);
                    TMA_LOAD_2D(ab2,           &mA, nc * 32, pixBase,           sb + ab * 8);
                    TMA_LOAD_2D(ab2 + A_BOX_B, &mA, nc * 32, pixBase + A_BOX_H, sb + ab * 8);
                }
            }
            if (u == 0)
                MBARRIER_WAIT_PARITY(sb + (c & 1) * 8, (c >> 1) & 1);
            MBARRIER_WAIT_PARITY(sb + 16 + s3r * 8, s3q);

            // ---- compute taps 2u, 2u+1 (skip tap 9) on chunk c ----
            const uint32_t Wb = sbW + s3r * W_STG_B;
            #pragma unroll
            for (int tt = 0; tt < 2; ++tt) {
                const int t = u * 2 + tt;
                if (t <= 8) {
                    const uint32_t Wtap = Wb + tt * W_PLANE_B;
                    const uint32_t Aofs = (uint32_t)(((t / 3) * 66 + (t % 3)) * ROWB);
                    #pragma unroll
                    for (int ks = 0; ks < 2; ++ks) {
                        uint32_t a0[4], a1r[4];
                        LDSM4(a0,  Ab + Aofs + a_base[0] + ks * 32);
                        LDSM4(a1r, Ab + Aofs + a_base[1] + ks * 32);
                        #pragma unroll
                        for (int nf = 0; nf < 4; ++nf) {
                            uint32_t bh[4];
                            LDSM4(bh, Wtap + b_off[nf] + ks * 32);
                            MMA16816(acc[0][nf * 2],     a0,  bh[0], bh[1]);
                            MMA16816(acc[0][nf * 2 + 1], a0,  bh[2], bh[3]);
                            MMA16816(acc[1][nf * 2],     a1r, bh[0], bh[1]);
                            MMA16816(acc[1][nf * 2 + 1], a1r, bh[2], bh[3]);
                        }
                    }
                }
            }
            if (lane == 0) {
                MBARRIER_ARRIVE(sb + 56 + s3r * 8);            // W stage consumed
                if (u == 4)
                    MBARRIER_ARRIVE(sb + 40 + (c & 1) * 8);    // A chunk consumed
            }
            if (++s3r == 3) { s3r = 0; s3q ^= 1; }
        }
    }

    // ---- epilogue ----
    const float ns = nscale[0];
    const float* __restrict__ dm = (CONV ? g_d2 : g_d1) + b * NTOT;
    const int q2 = (lane & 3) * 2;
    const int rr = lane >> 2;

    #pragma unroll
    for (int mf = 0; mf < 2; ++mf) {
        #pragma unroll
        for (int hf = 0; hf < 2; ++hf) {
            const int ml = wm * 32 + mf * 16 + rr + hf * 8;    // 0..127
            const int h  = R + (ml >> 6);
            const int w  = ml & 63;
            const float nz = noise[((size_t)b * H_SZ + h) * W_SZ + w] * ns;
            #pragma unroll
            for (int nf = 0; nf < 8; ++nf) {
                const int co = n0 + wn * 64 + nf * 8 + q2;
                float v0 = acc[mf][nf][hf * 2]     * dm[co]     + nz + bias[co];
                float v1 = acc[mf][nf][hf * 2 + 1] * dm[co + 1] + nz + bias[co + 1];
                v0 = (v0 > 0.f) ? v0 : 0.2f * v0;
                v1 = (v1 > 0.f) ? v1 : 0.2f * v1;
                if (CONV == 0) {
                    const float m0 = v0 * g_s2[b * CIN + co];
                    const float m1 = v1 * g_s2[b * CIN + co + 1];
                    const size_t o = ((size_t)(b * PW + h + 1) * PW + (w + 1)) * CIN + co;
                    *reinterpret_cast<__half2*>(g_x2p + o) =
                        __halves2half2(__float2half_rn(m0), __float2half_rn(m1));
                } else {
                    const int sh = co >> 8, sw = (co >> 7) & 1, c2 = co & 127;
                    float2 vv = make_float2(v0, v1);
                    *reinterpret_cast<float2*>(
                        outp + (((size_t)(b * 128 + 2 * h + sh)) * 128 + (2 * w + sw)) * 128 + c2) = vv;
                }
            }
        }
    }
}

// ---------------------------------------------------------------------------
// host
// ---------------------------------------------------------------------------
typedef CUresult (*PFN_tmap)(CUtensorMap*, CUtensorMapDataType, cuuint32_t, void*,
                             const cuuint64_t*, const cuuint64_t*, const cuuint32_t*,
                             const cuuint32_t*, CUtensorMapInterleave, CUtensorMapSwizzle,
                             CUtensorMapL2promotion, CUtensorMapFloatOOBfill);

static void encA(PFN_tmap fn, CUtensorMap* m, void* ptr)
{
    cuuint64_t dims[2]    = {CIN, NPIX};
    cuuint64_t strides[1] = {CIN * 2};
    cuuint32_t box[2]     = {40, A_BOX_H};
    cuuint32_t es[2]      = {1, 1};
    fn(m, CU_TENSOR_MAP_DATA_TYPE_FLOAT16, 2, ptr, dims, strides, box, es,
       CU_TENSOR_MAP_INTERLEAVE_NONE, CU_TENSOR_MAP_SWIZZLE_NONE,
       CU_TENSOR_MAP_L2_PROMOTION_L2_128B, CU_TENSOR_MAP_FLOAT_OOB_FILL_NONE);
}

static void encW(PFN_tmap fn, CUtensorMap* m, void* ptr, uint64_t ntot)
{
    cuuint64_t dims[3]    = {CIN, ntot, 9};
    cuuint64_t strides[2] = {CIN * 2, ntot * CIN * 2};
    cuuint32_t box[3]     = {40, 128, 2};
    cuuint32_t es[3]      = {1, 1, 1};
    fn(m, CU_TENSOR_MAP_DATA_TYPE_FLOAT16, 3, ptr, dims, strides, box, es,
       CU_TENSOR_MAP_INTERLEAVE_NONE, CU_TENSOR_MAP_SWIZZLE_NONE,
       CU_TENSOR_MAP_L2_PROMOTION_L2_128B, CU_TENSOR_MAP_FLOAT_OOB_FILL_NONE);
}

extern "C" void kernel_launch(void* const* d_in, const int* in_sizes, int n_in,
                              void* d_out, int out_size)
{
    const float* x    = (const float*)d_in[0];
    const float* w    = (const float*)d_in[1];
    const float* a1w  = (const float*)d_in[2];
    const float* a1b  = (const float*)d_in[3];
    const float* k1   = (const float*)d_in[4];
    const float* ns1  = (const float*)d_in[5];
    const float* b1   = (const float*)d_in[6];
    const float* a2w  = (const float*)d_in[7];
    const float* a2b  = (const float*)d_in[8];
    const float* k2   = (const float*)d_in[9];
    const float* ns2  = (const float*)d_in[10];
    const float* b2   = (const float*)d_in[11];
    const float* noi1 = (const float*)d_in[12];
    const float* noi2 = (const float*)d_in[13];
    float* outp = (float*)d_out;

    void* sym = nullptr;
    cudaDriverEntryPointQueryResult qres;
    cudaGetDriverEntryPoint("cuTensorMapEncodeTiled", &sym, cudaEnableDefault, &qres);
    PFN_tmap enc = (PFN_tmap)sym;

    void *pxp, *px2p, *pw1h, *pw2h;
    cudaGetSymbolAddress(&pxp,  g_xp);   cudaGetSymbolAddress(&px2p, g_x2p);
    cudaGetSymbolAddress(&pw1h, g_w1h);  cudaGetSymbolAddress(&pw2h, g_w2h);

    CUtensorMap mA1, mA2, mW1h, mW2h;
    encA(enc, &mA1, pxp);
    encA(enc, &mA2, px2p);
    encW(enc, &mW1h, pw1h, N1);
    encW(enc, &mW2h, pw2h, N2);

    cudaFuncSetAttribute(conv_mma<0>, cudaFuncAttributeMaxDynamicSharedMemorySize, SMEM_TOTAL);
    cudaFuncSetAttribute(conv_mma<1>, cudaFuncAttributeMaxDynamicSharedMemorySize, SMEM_TOTAL);

    // prep (5 launches; ncu -s 5 should land on conv1)
    { dim3 g(B_SZ, 2);  style_all<<<g, CIN>>>(w, a1w, a1b, a2w, a2b); }
    { dim3 g((CIN * N2 + 255) / 256, 2); ksq_all<<<g, 256>>>(k1, k2); }
    { dim3 g(6, B_SZ);  demod_all<<<g, 128>>>(); }
    { dim3 g(8, N2 / 64, 18); wsplit_all<<<g, 256>>>(k1, k2); }
    pad_kernel<<<NPIX / 4, 256>>>(x);

    // conv1: xp -> x2p (epilogue multiplies by s2, single fp16 plane)
    {
        dim3 grid(N1 / 128, 512);
        conv_mma<0><<<grid, 256, SMEM_TOTAL>>>(mA1, mW1h, noi1, ns1, b1, nullptr);
    }
    // conv2: x2p -> d_out (pixel shuffled)
    {
        dim3 grid(N2 / 128, 512);
        conv_mma<1><<<grid, 256, SMEM_TOTAL>>>(mA2, mW2h, noi2, ns2, b2, outp);
    }
}